// round 15
// baseline (speedup 1.0000x reference)
#include <cuda_runtime.h>
#include <cuda_bf16.h>
#include <math.h>

#define Bsz 32
#define Csz 129
#define Tsz 1000
#define Dsz 256
#define Nst 64
#define NL  4
#define FFTN 2048

// ---------------- scratch (device globals; no runtime alloc) ----------------
__device__ float  d_h [Bsz*Tsz*Dsz];     // final hidden (B,T,D) for pooling
__device__ float  d_xt2[Bsz*Tsz*Dsz];    // (B,D,T): normalized x OR conv z, in-place
__device__ float  d_nrm[Bsz*Tsz];        // per (b,t) L2 norm of LN output
__device__ float  d_k [NL*Dsz*Tsz];      // S4 kernels
__device__ float2 d_kf[NL*Dsz*FFTN];     // spectra of kernels (pre-scaled by 0.5/4096)
__device__ float  d_Ad[NL*Nst*Nst];
__device__ float  d_E [NL*Nst*Nst];      // Ad^8
__device__ float  d_twr[256];
__device__ float  d_twi[256];
__device__ float  d_wt[Csz*Dsz];         // transposed w_in
__device__ float  d_pe[Tsz*Dsz];         // positional encoding table

#define PI_D 3.14159265358979323846

// ---------------- complex helpers ----------------
struct C2 { float x, y; };
__device__ __forceinline__ C2 cmul(C2 a, C2 b){ C2 r; r.x = a.x*b.x - a.y*b.y; r.y = a.x*b.y + a.y*b.x; return r; }
__device__ __forceinline__ C2 cadd(C2 a, C2 b){ C2 r; r.x = a.x+b.x; r.y = a.y+b.y; return r; }
__device__ __forceinline__ C2 csub(C2 a, C2 b){ C2 r; r.x = a.x-b.x; r.y = a.y-b.y; return r; }
__device__ __forceinline__ C2 cmulni(C2 a){ C2 r; r.x = a.y; r.y = -a.x; return r; }  // a * (-i)

// padded complex (float2) smem index: conflict-free for strides 1/8/64
#define PDC(i) ((i) + ((i)>>4) + ((i)>>8))
#define CBUF 2200

// ---------------- f32x2 packed fma ----------------
__device__ __forceinline__ unsigned long long fma2(unsigned long long a, unsigned long long b, unsigned long long c){
    unsigned long long d;
    asm("fma.rn.f32x2 %0, %1, %2, %3;" : "=l"(d) : "l"(a), "l"(b), "l"(c));
    return d;
}
__device__ __forceinline__ float2 unpack2(unsigned long long v){
    float2 r; asm("mov.b64 {%0, %1}, %2;" : "=f"(r.x), "=f"(r.y) : "l"(v)); return r;
}

// ---------------- setup: twiddles, w transpose, pos-encoding ----------------
__global__ void setup_kernel(const float* __restrict__ w_in) {
    int idx = blockIdx.x * blockDim.x + threadIdx.x;
    int stride = gridDim.x * blockDim.x;
    if (idx < 256) {
        double ang = -2.0 * PI_D * (double)idx / (double)FFTN;
        d_twr[idx] = (float)cos(ang);
        d_twi[idx] = (float)sin(ang);
    }
    for (int i = idx; i < Csz*Dsz; i += stride) {
        int dd = i / Csz, c = i % Csz;
        d_wt[c*Dsz + dd] = w_in[i];
    }
    for (int i = idx; i < Tsz*Dsz; i += stride) {
        int t = i / Dsz, dd = i % Dsz;
        double divv = exp(-(double)(dd >> 1) * 2.0 * log(10000.0) / (double)Dsz);
        double arg = (double)t * divv;
        d_pe[i] = (float)((dd & 1) ? cos(arg) : sin(arg));
    }
}

// ---- Ad = solve(I - dtA, I + dtA) (pivot-free GJ) + E = Ad^8 (3 squarings) --
__global__ void compute_AdE_kernel(const float* __restrict__ s4_logdt) {
    int layer = blockIdx.x;
    __shared__ float M[64][65];
    __shared__ float R[64][65];
    __shared__ float fcol[64];
    __shared__ float rkM[64];
    __shared__ float rkR[64];
    int tid = threadIdx.x; // 512 threads

    float logdt = s4_logdt[layer*Dsz + 0];
    float dt = fminf(fmaxf(expf(logdt), 1e-4f), 0.1f);
    float hdt = dt * 0.5f;

    for (int idx = tid; idx < 64*64; idx += 512) {
        int i = idx >> 6, j = idx & 63;
        float Pi = sqrtf(1.0f + 2.0f*i), Pj = sqrtf(1.0f + 2.0f*j);
        float a;
        if (i == j)      a = -((float)i + 0.5f);
        else if (i > j)  a = -Pi*Pj;
        else             a =  Pi*Pj;
        float eye = (i == j) ? 1.0f : 0.0f;
        M[i][j] = eye - hdt*a;
        R[i][j] = eye + hdt*a;
    }
    __syncthreads();

    for (int k = 0; k < 64; k++) {
        float ipv = 1.0f / M[k][k];
        if (tid < 64) {
            fcol[tid] = (tid == k) ? 0.0f : M[tid][k] * ipv;
        } else if (tid < 128) {
            int c = tid - 64; rkM[c] = M[k][c];
        } else if (tid < 192) {
            int c = tid - 128; rkR[c] = R[k][c];
        }
        __syncthreads();
#pragma unroll
        for (int it = 0; it < 16; it++) {
            int e = tid + 512*it;
            int mat = e >> 12;
            int idx = e & 4095;
            int i = idx >> 6, j = idx & 63;
            if (mat == 0) {
                M[i][j] = (i == k) ? rkM[j]*ipv : M[i][j] - fcol[i]*rkM[j];
            } else {
                R[i][j] = (i == k) ? rkR[j]*ipv : R[i][j] - fcol[i]*rkR[j];
            }
        }
        __syncthreads();
    }
    // R = Ad. Write it, then square 3 times (using M as scratch) -> E = Ad^8.
    for (int idx = tid; idx < 64*64; idx += 512)
        d_Ad[layer*4096 + idx] = R[idx >> 6][idx & 63];
    __syncthreads();
    for (int rep = 0; rep < 3; rep++) {
        for (int idx = tid; idx < 4096; idx += 512) {
            int i = idx >> 6, j = idx & 63;
            float acc = 0.f;
#pragma unroll 8
            for (int k = 0; k < 64; k++) acc += R[i][k]*R[k][j];
            M[i][j] = acc;
        }
        __syncthreads();
        for (int idx = tid; idx < 4096; idx += 512)
            R[idx >> 6][idx & 63] = M[idx >> 6][idx & 63];
        __syncthreads();
    }
    for (int idx = tid; idx < 4096; idx += 512)
        d_E[layer*4096 + idx] = R[idx >> 6][idx & 63];
}

// ------- S4 recurrence -> d_k: inline W, then 8 outputs/iter via E = Ad^8 ---
// Clamps are provably inactive (contractive Cayley step, ||x_0|| ~ 0.6).
__global__ void s4_scan_kernel(const float* __restrict__ s4_B,
                               const float* __restrict__ s4_C) {
    int d = blockIdx.x, layer = blockIdx.y;
    int n = threadIdx.x;               // 64 threads
    __shared__ __align__(8) float xs[2][64];
    __shared__ float stage[2][64][9];
    __shared__ float wjs[64];
    // ---- W prologue: w_0 = b; w_{j+1} = Ad^T w_j ----
    float wv[8];
    {
        float adT[64];
#pragma unroll
        for (int m = 0; m < 64; m++) adT[m] = d_Ad[layer*4096 + m*64 + n];
        float w = s4_B[(layer*Nst + n)*Dsz + d];
        wv[0] = w;
        for (int j = 1; j < 8; j++) {
            wjs[n] = w;
            __syncthreads();
            float acc = 0.f;
#pragma unroll
            for (int m = 0; m < 64; m++) acc += adT[m]*wjs[m];
            w = acc;
            wv[j] = w;
            __syncthreads();
        }
    }
    // ---- E load ----
    unsigned long long e2[32];
    const float* Ep = d_E + layer*4096 + n*64;
#pragma unroll
    for (int j = 0; j < 32; j++) {
        float lo = Ep[2*j], hi = Ep[2*j+1];
        unsigned long long v;
        asm("mov.b64 %0, {%1, %2};" : "=l"(v) : "f"(lo), "f"(hi));
        e2[j] = v;
    }
    xs[0][n] = s4_C[(layer*Dsz + d)*Nst + n];
    __syncthreads();
    float* kp = d_k + (layer*Dsz + d)*Tsz;
    int g8 = n >> 3, j8 = n & 7;
    int cur = 0;
    for (int it = 0; it < 125; it++) {
        float x = xs[cur][n];
        int buf = it & 1;
#pragma unroll
        for (int j = 0; j < 8; j++) stage[buf][n][j] = x * wv[j];
        const unsigned long long* xv = reinterpret_cast<const unsigned long long*>(&xs[cur][0]);
        unsigned long long a0 = 0ULL, a1 = 0ULL, a2 = 0ULL, a3 = 0ULL;
#pragma unroll
        for (int j = 0; j < 8; j++) {
            a0 = fma2(e2[j],      xv[j],      a0);
            a1 = fma2(e2[j + 8],  xv[j + 8],  a1);
            a2 = fma2(e2[j + 16], xv[j + 16], a2);
            a3 = fma2(e2[j + 24], xv[j + 24], a3);
        }
        float2 f0 = unpack2(a0), f1 = unpack2(a1), f2 = unpack2(a2), f3 = unpack2(a3);
        float acc = ((f0.x + f0.y) + (f1.x + f1.y)) + ((f2.x + f2.y) + (f3.x + f3.y));
        xs[cur ^ 1][n] = fminf(fmaxf(acc, -100.0f), 100.0f);
        __syncthreads();
        float s = 0.f;
#pragma unroll
        for (int m = 0; m < 8; m++) s += stage[buf][j8 + 8*m][g8];
        s += __shfl_xor_sync(0xffffffffu, s, 4);
        s += __shfl_xor_sync(0xffffffffu, s, 2);
        s += __shfl_xor_sync(0xffffffffu, s, 1);
        if (j8 == 0) {
            int tt = it*8 + g8;
            float ks = fminf(fmaxf(s, -10.0f), 10.0f);
            kp[tt] = ks * expf(-0.01f * (float)tt);
        }
        cur ^= 1;
    }
}

// ---------------- radix-8 butterfly with twiddle ----------------
__device__ __forceinline__ void bf8(C2* v, C2 w1) {
    C2 t0 = cadd(v[0], v[4]), t1 = csub(v[0], v[4]);
    C2 t2 = cadd(v[2], v[6]), t3 = cmulni(csub(v[2], v[6]));
    C2 e0 = cadd(t0, t2), e1 = cadd(t1, t3), e2 = csub(t0, t2), e3 = csub(t1, t3);
    C2 u0 = cadd(v[1], v[5]), u1 = csub(v[1], v[5]);
    C2 u2 = cadd(v[3], v[7]), u3 = cmulni(csub(v[3], v[7]));
    C2 o0 = cadd(u0, u2), o1 = cadd(u1, u3), o2 = csub(u0, u2), o3 = csub(u1, u3);
    const float c = 0.70710678118654752440f;
    C2 q1; q1.x = c*(o1.x + o1.y); q1.y = c*(o1.y - o1.x);
    C2 q2 = cmulni(o2);
    C2 q3; q3.x = c*(o3.y - o3.x); q3.y = -c*(o3.x + o3.y);
    v[0] = cadd(e0, o0); v[1] = cadd(e1, q1); v[2] = cadd(e2, q2); v[3] = cadd(e3, q3);
    v[4] = csub(e0, o0); v[5] = csub(e1, q1); v[6] = csub(e2, q2); v[7] = csub(e3, q3);
    C2 w2 = cmul(w1, w1), w3 = cmul(w2, w1), w4 = cmul(w2, w2);
    C2 w5 = cmul(w4, w1), w6 = cmul(w4, w2), w7 = cmul(w4, w3);
    v[1] = cmul(v[1], w1); v[2] = cmul(v[2], w2); v[3] = cmul(v[3], w3);
    v[4] = cmul(v[4], w4); v[5] = cmul(v[5], w5); v[6] = cmul(v[6], w6); v[7] = cmul(v[7], w7);
}

// radix-8 butterfly with upper 4 inputs == 0 (bit-identical to bf8 on zeros)
__device__ __forceinline__ void bf8h(C2* v, C2 w1) {
    C2 a0 = v[0], a1 = v[1], a2 = v[2], a3 = v[3];
    C2 e0 = cadd(a0, a2);
    C2 e1; e1.x = a0.x + a2.y; e1.y = a0.y - a2.x;   // a0 + (-i)a2
    C2 e2 = csub(a0, a2);
    C2 e3; e3.x = a0.x - a2.y; e3.y = a0.y + a2.x;   // a0 + (i)a2
    C2 o0 = cadd(a1, a3);
    C2 o1; o1.x = a1.x + a3.y; o1.y = a1.y - a3.x;
    C2 o2 = csub(a1, a3);
    C2 o3; o3.x = a1.x - a3.y; o3.y = a1.y + a3.x;
    const float c = 0.70710678118654752440f;
    C2 q1; q1.x = c*(o1.x + o1.y); q1.y = c*(o1.y - o1.x);
    C2 q2 = cmulni(o2);
    C2 q3; q3.x = c*(o3.y - o3.x); q3.y = -c*(o3.x + o3.y);
    v[0] = cadd(e0, o0); v[1] = cadd(e1, q1); v[2] = cadd(e2, q2); v[3] = cadd(e3, q3);
    v[4] = csub(e0, o0); v[5] = csub(e1, q1); v[6] = csub(e2, q2); v[7] = csub(e3, q3);
    C2 w2 = cmul(w1, w1), w3 = cmul(w2, w1), w4 = cmul(w2, w2);
    C2 w5 = cmul(w4, w1), w6 = cmul(w4, w2), w7 = cmul(w4, w3);
    v[1] = cmul(v[1], w1); v[2] = cmul(v[2], w2); v[3] = cmul(v[3], w3);
    v[4] = cmul(v[4], w4); v[5] = cmul(v[5], w5); v[6] = cmul(v[6], w6); v[7] = cmul(v[7], w7);
}

// one Stockham radix-8 stage on float2 buffers
__device__ __forceinline__ void stage8c(const float2* __restrict__ s, float2* __restrict__ d,
                                        const float2* __restrict__ tw,
                                        int p, int q, int st) {
    C2 v[8];
    int base = q + st*p;
#pragma unroll
    for (int k = 0; k < 8; k++) {
        float2 u = s[PDC(base + 256*k)];
        v[k].x = u.x; v[k].y = u.y;
    }
    float2 tv = tw[PDC(p*st)];
    C2 w1; w1.x = tv.x; w1.y = tv.y;
    bf8(v, w1);
    int wb = q + 8*st*p;
#pragma unroll
    for (int k = 0; k < 8; k++)
        d[PDC(wb + st*k)] = make_float2(v[k].x, v[k].y);
}

// shared tail: stages 2,3 + final radix-4 (Q holds stage-1 output)
__device__ __forceinline__ void fft2048c_tail(float2* P, float2* Q,
                                              const float2* __restrict__ tw) {
    int tid = threadIdx.x;
    __syncthreads();
    stage8c(Q, P, tw, tid & 31, tid >> 5, 8); // n=256, s=8
    __syncthreads();
    stage8c(P, Q, tw, tid >> 6, tid & 63, 64);// n=32, s=64
    __syncthreads();
    // radix-4, s=512, no twiddle; 2 butterflies/thread, Q -> P
#pragma unroll
    for (int h = 0; h < 2; h++) {
        int q = tid + 256*h;
        float2 u0 = Q[PDC(q)], u1 = Q[PDC(q + 512)];
        float2 u2 = Q[PDC(q + 1024)], u3 = Q[PDC(q + 1536)];
        C2 x0; x0.x = u0.x; x0.y = u0.y;
        C2 x1; x1.x = u1.x; x1.y = u1.y;
        C2 x2; x2.x = u2.x; x2.y = u2.y;
        C2 x3; x3.x = u3.x; x3.y = u3.y;
        C2 t0 = cadd(x0, x2), t1 = csub(x0, x2);
        C2 t2 = cadd(x1, x3), t3 = cmulni(csub(x1, x3));
        P[PDC(q)]        = make_float2(t0.x + t2.x, t0.y + t2.y);
        P[PDC(q + 512)]  = make_float2(t1.x + t3.x, t1.y + t3.y);
        P[PDC(q + 1024)] = make_float2(t0.x - t2.x, t0.y - t2.y);
        P[PDC(q + 1536)] = make_float2(t1.x - t3.x, t1.y - t3.y);
    }
    __syncthreads();   // result visible
}

// full 2048 FFT (general input): input AND result in P; Q scratch. 256 thr.
__device__ __forceinline__ void fft2048c(float2* P, float2* Q,
                                         const float2* __restrict__ tw) {
    int tid = threadIdx.x;
    __syncthreads();   // input visible
    stage8c(P, Q, tw, tid, 0, 1);             // n=2048, s=1
    fft2048c_tail(P, Q, tw);
}

// forward 2048 FFT for inputs zero on [1024,2048): only P[0,1024) is read.
__device__ __forceinline__ void fft2048c_fwd(float2* P, float2* Q,
                                             const float2* __restrict__ tw) {
    int tid = threadIdx.x;
    __syncthreads();   // input visible
    {
        C2 v[8];
#pragma unroll
        for (int k = 0; k < 4; k++) {
            float2 u = P[PDC(tid + 256*k)];
            v[k].x = u.x; v[k].y = u.y;
        }
        float2 tv = tw[PDC(tid)];
        C2 w1; w1.x = tv.x; w1.y = tv.y;
        bf8h(v, w1);
        int wb = 8*tid;
#pragma unroll
        for (int k = 0; k < 8; k++)
            Q[PDC(wb + k)] = make_float2(v[k].x, v[k].y);
    }
    fft2048c_tail(P, Q, tw);
}

// ---------------- kernel spectra: pack 2 d's per FFT ----------------
// stored K pre-scaled by 0.5 (unpack) * 0.5 (X-unpack fold) * 1/2048 (ifft)
#define KSCL (0.5f/4096.0f)
__global__ void fft_k_kernel() {
    __shared__ float2 A[CBUF], Bc[CBUF];
    __shared__ float2 tws[280];
    int tid = threadIdx.x;
    int dp = blockIdx.x, layer = blockIdx.y;
    int d0 = dp*2, d1 = dp*2 + 1;
    tws[PDC(tid)] = make_float2(d_twr[tid], d_twi[tid]);
    const float* k0 = d_k + (layer*Dsz + d0)*Tsz;
    const float* k1 = d_k + (layer*Dsz + d1)*Tsz;
#pragma unroll
    for (int q = 0; q < 4; q++) {
        int t = tid + 256*q;
        float v0 = (t < Tsz) ? k0[t] : 0.0f;
        float v1 = (t < Tsz) ? k1[t] : 0.0f;
        A[PDC(t)] = make_float2(v0, v1);
    }
    fft2048c_fwd(A, Bc, tws);
    float2* K0 = d_kf + (layer*Dsz + d0)*FFTN;
    float2* K1 = d_kf + (layer*Dsz + d1)*FFTN;
#pragma unroll
    for (int q = 0; q < 8; q++) {
        int f = tid + 256*q;
        int fm = (FFTN - f) & (FFTN - 1);
        float2 Zf = A[PDC(f)];
        float2 Zm = A[PDC(fm)];
        K0[f] = make_float2(KSCL*(Zf.x + Zm.x), KSCL*(Zf.y - Zm.y));
        K1[f] = make_float2(KSCL*(Zf.y + Zm.y), KSCL*(Zm.x - Zf.x));
    }
}

// ---- input projection + LN + pos-enc + L2-normalize -> d_xt2 (B,D,T) -------
// 128 threads; each owns 2 d's (tid, tid+128); x tile staged as float2 pairs.
__global__ void in_proj_ln_kernel(const float* __restrict__ x,
                                  const float* __restrict__ b_in,
                                  const float* __restrict__ g,
                                  const float* __restrict__ bbp) {
    int b = blockIdx.x, t0 = blockIdx.y * 20;
    int tid = threadIdx.x;          // 128
    int lane = tid & 31, w = tid >> 5;   // 4 warps
    int d0 = tid, d1 = tid + 128;
    __shared__ float ws[32][256];
    __shared__ __align__(8) float2 xs2[32][10];
    __shared__ float red1[4][20], red2[4][20];
    __shared__ float msh[20], ish[20];
    float acc0[20], acc1[20];
#pragma unroll
    for (int j = 0; j < 20; j++) { acc0[j] = 0.0f; acc1[j] = 0.0f; }
    for (int c0 = 0; c0 < Csz; c0 += 32) {
        __syncthreads();
        for (int l = tid; l < 32*256; l += 128) {
            int i = l >> 8, col = l & 255;
            ws[i][col] = (c0 + i < Csz) ? d_wt[(c0 + i)*Dsz + col] : 0.0f;
        }
        // x rows are float2-aligned: base (b*Csz+cc)*Tsz + t0, both even
        for (int l = tid; l < 320; l += 128) {
            int cc = l / 10, jp = l % 10;
            xs2[cc][jp] = (c0 + cc < Csz)
                ? *reinterpret_cast<const float2*>(x + (b*Csz + c0 + cc)*Tsz + t0 + 2*jp)
                : make_float2(0.f, 0.f);
        }
        __syncthreads();
#pragma unroll 4
        for (int cc = 0; cc < 32; cc++) {
            float w0 = ws[cc][d0];
            float w1 = ws[cc][d1];
#pragma unroll
            for (int jp = 0; jp < 10; jp++) {
                float2 xv = xs2[cc][jp];
                acc0[2*jp]   += w0 * xv.x;
                acc0[2*jp+1] += w0 * xv.y;
                acc1[2*jp]   += w1 * xv.x;
                acc1[2*jp+1] += w1 * xv.y;
            }
        }
    }
    float bias0 = b_in[d0], bias1 = b_in[d1];
#pragma unroll
    for (int j = 0; j < 20; j++) { acc0[j] += bias0; acc1[j] += bias1; }
    // block reduction 1: mean / var per t
#pragma unroll
    for (int j = 0; j < 20; j++) {
        float sv = acc0[j] + acc1[j];
        float sq = acc0[j]*acc0[j] + acc1[j]*acc1[j];
#pragma unroll
        for (int off = 16; off; off >>= 1) {
            sv += __shfl_xor_sync(0xffffffffu, sv, off);
            sq += __shfl_xor_sync(0xffffffffu, sq, off);
        }
        if (lane == 0) { red1[w][j] = sv; red2[w][j] = sq; }
    }
    __syncthreads();
    if (tid < 20) {
        float S = 0.f, Q = 0.f;
        for (int ww = 0; ww < 4; ww++) { S += red1[ww][tid]; Q += red2[ww][tid]; }
        float m = S * (1.0f/256.0f);
        float var = Q * (1.0f/256.0f) - m*m;
        msh[tid] = m; ish[tid] = rsqrtf(var + 1e-5f);
    }
    __syncthreads();
    float g0 = g[d0], g1 = g[d1], bv0 = bbp[d0], bv1 = bbp[d1];
#pragma unroll
    for (int j = 0; j < 20; j++) {
        float m = msh[j], is = ish[j];
        acc0[j] = (acc0[j] - m)*is*g0 + bv0 + d_pe[(t0 + j)*Dsz + d0];
        acc1[j] = (acc1[j] - m)*is*g1 + bv1 + d_pe[(t0 + j)*Dsz + d1];
    }
    // block reduction 2: L2 norm per t
#pragma unroll
    for (int j = 0; j < 20; j++) {
        float sq = acc0[j]*acc0[j] + acc1[j]*acc1[j];
#pragma unroll
        for (int off = 16; off; off >>= 1)
            sq += __shfl_xor_sync(0xffffffffu, sq, off);
        if (lane == 0) red1[w][j] = sq;
    }
    __syncthreads();
    if (tid < 20) {
        float Q = 0.f;
        for (int ww = 0; ww < 4; ww++) Q += red1[ww][tid];
        float nrm = sqrtf(Q) + 1e-8f;
        d_nrm[b*Tsz + t0 + tid] = nrm;
        ish[tid] = 1.0f / nrm;
    }
    __syncthreads();
#pragma unroll
    for (int j = 0; j < 20; j++) { acc0[j] *= ish[j]; acc1[j] *= ish[j]; }
    float4* op0 = reinterpret_cast<float4*>(d_xt2 + ((size_t)b*Dsz + d0)*Tsz + t0);
    float4* op1 = reinterpret_cast<float4*>(d_xt2 + ((size_t)b*Dsz + d1)*Tsz + t0);
#pragma unroll
    for (int q = 0; q < 5; q++) {
        op0[q] = make_float4(acc0[4*q], acc0[4*q+1], acc0[4*q+2], acc0[4*q+3]);
        op1[q] = make_float4(acc1[4*q], acc1[4*q+1], acc1[4*q+2], acc1[4*q+3]);
    }
}

// -------- FFT conv + gate + gelu + residual (z = gelu(y)+1.1h), in-place ----
// Thread owns t in [4*tid, 4*tid+4): tid<250 exactly covers Tsz=1000.
// K spectra + gates prefetched before the forward FFT to hide L2 latency.
__global__ void fft_conv_kernel(int layer, const float* __restrict__ s4_D) {
    __shared__ float2 A[CBUF], Bc[CBUF];
    __shared__ float2 tws[280];
    int tid = threadIdx.x;
    int b = blockIdx.x, dp = blockIdx.y;
    int d0 = dp*2, d1 = dp*2 + 1;
    tws[PDC(tid)] = make_float2(d_twr[tid], d_twi[tid]);
    float* x0 = d_xt2 + ((size_t)b*Dsz + d0)*Tsz;
    float* x1 = d_xt2 + ((size_t)b*Dsz + d1)*Tsz;
    const float* np = d_nrm + b*Tsz;
    const float2* K0 = d_kf + (layer*Dsz + d0)*FFTN;
    const float2* K1 = d_kf + (layer*Dsz + d1)*FFTN;
    // ---- prefetch (issued before FFT; consumed after) ----
    float2 pk0[4], pk1[4];
#pragma unroll
    for (int q = 0; q < 4; q++) {
        int f = tid + 256*q;
        pk0[q] = K0[f];
        pk1[q] = K1[f];
    }
    float2 pk0m, pk1m;
    if (tid == 0) { pk0m = K0[1024]; pk1m = K1[1024]; }
    float sD0 = s4_D[layer*Dsz + d0];
    float sD1 = s4_D[layer*Dsz + d1];
    int t4 = tid * 4;
    bool valid = (t4 < Tsz);
    float4 fx0, fx1, fnr;
    if (valid) {
        fx0 = *reinterpret_cast<const float4*>(x0 + t4);
        fx1 = *reinterpret_cast<const float4*>(x1 + t4);
        fnr = *reinterpret_cast<const float4*>(np + t4);
    } else {
        fx0 = make_float4(0.f,0.f,0.f,0.f);
        fx1 = fx0; fnr = fx0;
    }
    // stage input into [0,1024) only; fwd FFT never reads the upper half
    if (t4 < 1024) {
        A[PDC(t4 + 0)] = make_float2(fx0.x, fx1.x);
        A[PDC(t4 + 1)] = make_float2(fx0.y, fx1.y);
        A[PDC(t4 + 2)] = make_float2(fx0.z, fx1.z);
        A[PDC(t4 + 3)] = make_float2(fx0.w, fx1.w);
    }
    fft2048c_fwd(A, Bc, tws);   // Z in A
    // spectral multiply with conjugate symmetry: f in [0,1024), dual write
#pragma unroll
    for (int q = 0; q < 4; q++) {
        int f = tid + 256*q;
        int fm = (FFTN - f) & (FFTN - 1);
        float2 Zf = A[PDC(f)];
        float2 Zm = A[PDC(fm)];
        C2 X0; X0.x = Zf.x + Zm.x; X0.y = Zf.y - Zm.y;
        C2 X1; X1.x = Zf.y + Zm.y; X1.y = Zm.x - Zf.x;
        C2 c0; c0.x = pk0[q].x; c0.y = pk0[q].y;
        C2 c1; c1.x = pk1[q].x; c1.y = pk1[q].y;
        C2 Y0 = cmul(X0, c0);
        C2 Y1 = cmul(X1, c1);
        Bc[PDC(f)]  = make_float2(Y0.x - Y1.y, -(Y0.y + Y1.x));  // conj(S)(f)
        Bc[PDC(fm)] = make_float2(Y0.x + Y1.y,   Y0.y - Y1.x);   // conj(S)(fm)
    }
    if (tid == 0) {   // self-conjugate bin f = 1024
        float2 Zf = A[PDC(1024)];
        C2 X0; X0.x = 2.0f*Zf.x; X0.y = 0.0f;
        C2 X1; X1.x = 2.0f*Zf.y; X1.y = 0.0f;
        C2 c0; c0.x = pk0m.x; c0.y = pk0m.y;
        C2 c1; c1.x = pk1m.x; c1.y = pk1m.y;
        C2 Y0 = cmul(X0, c0);
        C2 Y1 = cmul(X1, c1);
        Bc[PDC(1024)] = make_float2(Y0.x - Y1.y, -(Y0.y + Y1.x));
    }
    fft2048c(Bc, A, tws);   // V in Bc (scale folded into K); ifft = conj(V)
    float gate0 = 1.0f / (1.0f + expf(-sD0));
    float gate1 = 1.0f / (1.0f + expf(-sD1));
    if (valid) {
        float2 V0 = Bc[PDC(t4 + 0)];
        float2 V1 = Bc[PDC(t4 + 1)];
        float2 V2 = Bc[PDC(t4 + 2)];
        float2 V3 = Bc[PDC(t4 + 3)];
        float4 r0, r1;
        {
            float y0 =  V0.x + fx0.x*gate0, y1 = -V0.y + fx1.x*gate1;
            r0.x = 0.5f*y0*(1.0f + erff(y0*0.70710678118654752f)) + 1.1f*fx0.x*fnr.x;
            r1.x = 0.5f*y1*(1.0f + erff(y1*0.70710678118654752f)) + 1.1f*fx1.x*fnr.x;
        }
        {
            float y0 =  V1.x + fx0.y*gate0, y1 = -V1.y + fx1.y*gate1;
            r0.y = 0.5f*y0*(1.0f + erff(y0*0.70710678118654752f)) + 1.1f*fx0.y*fnr.y;
            r1.y = 0.5f*y1*(1.0f + erff(y1*0.70710678118654752f)) + 1.1f*fx1.y*fnr.y;
        }
        {
            float y0 =  V2.x + fx0.z*gate0, y1 = -V2.y + fx1.z*gate1;
            r0.z = 0.5f*y0*(1.0f + erff(y0*0.70710678118654752f)) + 1.1f*fx0.z*fnr.z;
            r1.z = 0.5f*y1*(1.0f + erff(y1*0.70710678118654752f)) + 1.1f*fx1.z*fnr.z;
        }
        {
            float y0 =  V3.x + fx0.w*gate0, y1 = -V3.y + fx1.w*gate1;
            r0.w = 0.5f*y0*(1.0f + erff(y0*0.70710678118654752f)) + 1.1f*fx0.w*fnr.w;
            r1.w = 0.5f*y1*(1.0f + erff(y1*0.70710678118654752f)) + 1.1f*fx1.w*fnr.w;
        }
        *reinterpret_cast<float4*>(x0 + t4) = r0;
        *reinterpret_cast<float4*>(x1 + t4) = r1;
    }
}

// ---- post: LN(z); last -> d_h (B,T,D); else normalized transposed + norms --
__global__ void post_ln_norm_t_kernel(int layer, int last,
                                      const float* __restrict__ ln_g,
                                      const float* __restrict__ ln_b) {
    __shared__ float tile[32][257];
    int b = blockIdx.x, t0 = blockIdx.y * 32;
    int tid = threadIdx.x, lane = tid & 31, w = tid >> 5;
#pragma unroll
    for (int i = 0; i < 32; i++) {
        int dd = i*8 + w;
        int t = t0 + lane;
        tile[lane][dd] = (t < Tsz) ? d_xt2[((size_t)b*Dsz + dd)*Tsz + t] : 0.0f;
    }
    __syncthreads();
    const float* g  = ln_g + layer*Dsz;
    const float* bb = ln_b + layer*Dsz;
#pragma unroll
    for (int j = 0; j < 4; j++) {
        int r = w + 8*j;
        int t = t0 + r;
        if (t >= Tsz) continue;
        float z[8]; float s = 0.f, s2 = 0.f;
#pragma unroll
        for (int k = 0; k < 8; k++) {
            float zz = tile[r][lane + 32*k];
            z[k] = zz; s += zz; s2 += zz*zz;
        }
#pragma unroll
        for (int off = 16; off; off >>= 1) {
            s  += __shfl_xor_sync(0xffffffffu, s,  off);
            s2 += __shfl_xor_sync(0xffffffffu, s2, off);
        }
        float m = s * (1.0f/256.0f);
        float var = s2 * (1.0f/256.0f) - m*m;
        float is = rsqrtf(var + 1e-5f);
        if (last) {
            float* hp = d_h + ((size_t)b*Tsz + t)*Dsz;
#pragma unroll
            for (int k = 0; k < 8; k++) {
                int dd = lane + 32*k;
                hp[dd] = (z[k] - m)*is*g[dd] + bb[dd];
            }
        } else {
            float o[8]; float ss = 0.f;
#pragma unroll
            for (int k = 0; k < 8; k++) {
                int dd = lane + 32*k;
                float ov = (z[k] - m)*is*g[dd] + bb[dd];
                o[k] = ov; ss += ov*ov;
            }
#pragma unroll
            for (int off = 16; off; off >>= 1) ss += __shfl_xor_sync(0xffffffffu, ss, off);
            float nrm = sqrtf(ss) + 1e-8f;
            float invn = 1.0f / nrm;
            if (lane == 0) d_nrm[b*Tsz + t] = nrm;
#pragma unroll
            for (int k = 0; k < 8; k++) tile[r][lane + 32*k] = o[k]*invn;
        }
    }
    if (last) return;
    __syncthreads();
#pragma unroll
    for (int i = 0; i < 32; i++) {
        int dd = i*8 + w;
        int t = t0 + lane;
        if (t < Tsz) d_xt2[((size_t)b*Dsz + dd)*Tsz + t] = tile[lane][dd];
    }
}

// ---------------- fused MHA pooling + head ----------------
__global__ void pool_head_kernel(const float* __restrict__ cls,
                                 const float* __restrict__ in_w,
                                 const float* __restrict__ in_b,
                                 const float* __restrict__ out_w,
                                 const float* __restrict__ out_b,
                                 const float* __restrict__ hw1,
                                 const float* __restrict__ hb1,
                                 const float* __restrict__ hw2,
                                 const float* __restrict__ hb2,
                                 float* __restrict__ out) {
    int b = blockIdx.x;
    int tid = threadIdx.x, lane = tid & 31, w = tid >> 5;
    __shared__ float Q[256];
    __shared__ float vp[8][256];
    __shared__ float sc[8][1001];
    __shared__ float ch[8];
    __shared__ float red[256];
    __shared__ float hsm[128];

    {
        float acc = in_b[tid];
        for (int c = 0; c < 256; c++) acc += cls[c] * in_w[tid*256 + c];
        Q[tid] = acc;
    }
    __syncthreads();
#pragma unroll
    for (int h = 0; h < 8; h++) {
        float acc = 0.f;
#pragma unroll
        for (int i = 0; i < 32; i++)
            acc += in_w[(256 + h*32 + i)*256 + tid] * Q[h*32 + i];
        vp[h][tid] = acc;
    }
    if (tid < 8) {
        float acc = 0.f;
        for (int i = 0; i < 32; i++) acc += in_b[256 + tid*32 + i] * Q[tid*32 + i];
        ch[tid] = acc;
    }
    __syncthreads();
    const float iss = 0.17677669529663687f; // 1/sqrt(32)
    for (int s = w; s < 1001; s += 8) {
        const float* kvr = (s == 0) ? cls : (d_h + ((size_t)b*Tsz + s - 1)*Dsz);
        float xv[8];
#pragma unroll
        for (int k = 0; k < 8; k++) xv[k] = kvr[lane*8 + k];
#pragma unroll
        for (int h = 0; h < 8; h++) {
            float a = 0.f;
#pragma unroll
            for (int k = 0; k < 8; k++) a += xv[k] * vp[h][lane*8 + k];
#pragma unroll
            for (int off = 16; off; off >>= 1) a += __shfl_xor_sync(0xffffffffu, a, off);
            if (lane == h) sc[h][s] = (a + ch[h]) * iss;
        }
    }
    __syncthreads();
    {
        int h = w;
        float mx = -1e30f;
        for (int s = lane; s < 1001; s += 32) mx = fmaxf(mx, sc[h][s]);
#pragma unroll
        for (int off = 16; off; off >>= 1) mx = fmaxf(mx, __shfl_xor_sync(0xffffffffu, mx, off));
        float sum = 0.f;
        for (int s = lane; s < 1001; s += 32) { float e = expf(sc[h][s] - mx); sc[h][s] = e; sum += e; }
#pragma unroll
        for (int off = 16; off; off >>= 1) sum += __shfl_xor_sync(0xffffffffu, sum, off);
        float invs = 1.0f / sum;
        for (int s = lane; s < 1001; s += 32) sc[h][s] *= invs;
    }
    __syncthreads();
    float pj[8];
#pragma unroll
    for (int h = 0; h < 8; h++) pj[h] = 0.f;
    for (int s = 0; s < 1001; s++) {
        float kvv = (s == 0) ? cls[tid] : d_h[((size_t)b*Tsz + s - 1)*Dsz + tid];
#pragma unroll
        for (int h = 0; h < 8; h++) pj[h] += sc[h][s] * kvv;
    }
    __syncthreads();
#pragma unroll
    for (int h = 0; h < 8; h++) vp[h][tid] = pj[h];
    __syncthreads();
    {
        int h = tid >> 5;
        float acc = in_b[512 + tid];
        for (int j = 0; j < 256; j++) acc += in_w[(512 + tid)*256 + j] * vp[h][j];
        Q[tid] = acc;
    }
    __syncthreads();
    {
        float acc = out_b[tid];
        for (int i = 0; i < 256; i++) acc += out_w[tid*256 + i] * Q[i];
        red[tid] = acc;
    }
    __syncthreads();
    if (tid < 128) {
        float acc = hb1[tid];
        for (int i = 0; i < 256; i++) acc += hw1[tid*256 + i] * red[i];
        hsm[tid] = fmaxf(acc, 0.0f);
    }
    __syncthreads();
    if (w == 0) {
        float a = 0.f;
#pragma unroll
        for (int k = 0; k < 4; k++) a += hsm[lane + 32*k] * hw2[lane + 32*k];
#pragma unroll
        for (int off = 16; off; off >>= 1) a += __shfl_xor_sync(0xffffffffu, a, off);
        if (lane == 0) out[b] = a + hb2[0];
    }
}

// ---------------- launch ----------------
extern "C" void kernel_launch(void* const* d_in, const int* in_sizes, int n_in,
                              void* d_out, int out_size) {
    const float* x        = (const float*)d_in[0];
    const float* w_in     = (const float*)d_in[1];
    const float* b_in     = (const float*)d_in[2];
    const float* ln_in_g  = (const float*)d_in[3];
    const float* ln_in_b  = (const float*)d_in[4];
    const float* s4_B     = (const float*)d_in[5];
    const float* s4_C     = (const float*)d_in[6];
    const float* s4_logdt = (const float*)d_in[7];
    const float* s4_D     = (const float*)d_in[8];
    const float* ln_g     = (const float*)d_in[9];
    const float* ln_b     = (const float*)d_in[10];
    const float* cls      = (const float*)d_in[11];
    const float* mha_in_w = (const float*)d_in[12];
    const float* mha_in_b = (const float*)d_in[13];
    const float* mha_out_w= (const float*)d_in[14];
    const float* mha_out_b= (const float*)d_in[15];
    const float* head_w1  = (const float*)d_in[16];
    const float* head_b1  = (const float*)d_in[17];
    const float* head_w2  = (const float*)d_in[18];
    const float* head_b2  = (const float*)d_in[19];
    float* out = (float*)d_out;

    setup_kernel<<<256, 256>>>(w_in);
    compute_AdE_kernel<<<NL, 512>>>(s4_logdt);
    s4_scan_kernel<<<dim3(Dsz, NL), 64>>>(s4_B, s4_C);
    fft_k_kernel<<<dim3(Dsz/2, NL), 256>>>();
    in_proj_ln_kernel<<<dim3(Bsz, 50), 128>>>(x, b_in, ln_in_g, ln_in_b);
    for (int layer = 0; layer < NL; layer++) {
        fft_conv_kernel<<<dim3(Bsz, Dsz/2), 256>>>(layer, s4_D);
        post_ln_norm_t_kernel<<<dim3(Bsz, 32), 256>>>(layer, (layer == NL-1) ? 1 : 0, ln_g, ln_b);
    }
    pool_head_kernel<<<Bsz, 256>>>(cls, mha_in_w, mha_in_b, mha_out_w, mha_out_b,
                                   head_w1, head_b1, head_w2, head_b2, out);
}

// round 16
// speedup vs baseline: 1.0134x; 1.0134x over previous
#include <cuda_runtime.h>
#include <cuda_bf16.h>
#include <math.h>

#define Bsz 32
#define Csz 129
#define Tsz 1000
#define Dsz 256
#define Nst 64
#define NL  4
#define FFTN 2048

// ---------------- scratch (device globals; no runtime alloc) ----------------
__device__ float  d_h [Bsz*Tsz*Dsz];     // final hidden (B,T,D) for pooling
__device__ float  d_xt2[Bsz*Tsz*Dsz];    // (B,D,T): normalized x OR conv z, in-place
__device__ float  d_nrm[Bsz*Tsz];        // per (b,t) L2 norm of LN output
__device__ float  d_k [NL*Dsz*Tsz];      // S4 kernels
__device__ float2 d_kf[NL*Dsz*FFTN];     // spectra of kernels (pre-scaled by 0.5/4096)
__device__ float  d_Ad[NL*Nst*Nst];
__device__ float  d_E [NL*Nst*Nst];      // Ad^8
__device__ float  d_twr[256];
__device__ float  d_twi[256];
__device__ float  d_wt[Csz*Dsz];         // transposed w_in
__device__ float  d_pe[Tsz*Dsz];         // positional encoding table

#define PI_D 3.14159265358979323846

// ---------------- complex helpers ----------------
struct C2 { float x, y; };
__device__ __forceinline__ C2 cmul(C2 a, C2 b){ C2 r; r.x = a.x*b.x - a.y*b.y; r.y = a.x*b.y + a.y*b.x; return r; }
__device__ __forceinline__ C2 cadd(C2 a, C2 b){ C2 r; r.x = a.x+b.x; r.y = a.y+b.y; return r; }
__device__ __forceinline__ C2 csub(C2 a, C2 b){ C2 r; r.x = a.x-b.x; r.y = a.y-b.y; return r; }
__device__ __forceinline__ C2 cmulni(C2 a){ C2 r; r.x = a.y; r.y = -a.x; return r; }  // a * (-i)

// padded complex (float2) smem index: conflict-free for strides 1/8/64
#define PDC(i) ((i) + ((i)>>4) + ((i)>>8))
#define CBUF 2200

// ---------------- f32x2 packed fma ----------------
__device__ __forceinline__ unsigned long long fma2(unsigned long long a, unsigned long long b, unsigned long long c){
    unsigned long long d;
    asm("fma.rn.f32x2 %0, %1, %2, %3;" : "=l"(d) : "l"(a), "l"(b), "l"(c));
    return d;
}
__device__ __forceinline__ float2 unpack2(unsigned long long v){
    float2 r; asm("mov.b64 {%0, %1}, %2;" : "=f"(r.x), "=f"(r.y) : "l"(v)); return r;
}

// ---------------- setup: twiddles, w transpose, pos-encoding ----------------
__global__ void setup_kernel(const float* __restrict__ w_in) {
    int idx = blockIdx.x * blockDim.x + threadIdx.x;
    int stride = gridDim.x * blockDim.x;
    if (idx < 256) {
        double ang = -2.0 * PI_D * (double)idx / (double)FFTN;
        d_twr[idx] = (float)cos(ang);
        d_twi[idx] = (float)sin(ang);
    }
    for (int i = idx; i < Csz*Dsz; i += stride) {
        int dd = i / Csz, c = i % Csz;
        d_wt[c*Dsz + dd] = w_in[i];
    }
    for (int i = idx; i < Tsz*Dsz; i += stride) {
        int t = i / Dsz, dd = i % Dsz;
        double divv = exp(-(double)(dd >> 1) * 2.0 * log(10000.0) / (double)Dsz);
        double arg = (double)t * divv;
        d_pe[i] = (float)((dd & 1) ? cos(arg) : sin(arg));
    }
}

// ---- Ad = solve(I - dtA, I + dtA) (pivot-free GJ) + E = Ad^8 (3 squarings) --
__global__ void compute_AdE_kernel(const float* __restrict__ s4_logdt) {
    int layer = blockIdx.x;
    __shared__ float M[64][65];
    __shared__ float R[64][65];
    __shared__ float fcol[64];
    __shared__ float rkM[64];
    __shared__ float rkR[64];
    int tid = threadIdx.x; // 512 threads

    float logdt = s4_logdt[layer*Dsz + 0];
    float dt = fminf(fmaxf(expf(logdt), 1e-4f), 0.1f);
    float hdt = dt * 0.5f;

    for (int idx = tid; idx < 64*64; idx += 512) {
        int i = idx >> 6, j = idx & 63;
        float Pi = sqrtf(1.0f + 2.0f*i), Pj = sqrtf(1.0f + 2.0f*j);
        float a;
        if (i == j)      a = -((float)i + 0.5f);
        else if (i > j)  a = -Pi*Pj;
        else             a =  Pi*Pj;
        float eye = (i == j) ? 1.0f : 0.0f;
        M[i][j] = eye - hdt*a;
        R[i][j] = eye + hdt*a;
    }
    __syncthreads();

    for (int k = 0; k < 64; k++) {
        float ipv = 1.0f / M[k][k];
        if (tid < 64) {
            fcol[tid] = (tid == k) ? 0.0f : M[tid][k] * ipv;
        } else if (tid < 128) {
            int c = tid - 64; rkM[c] = M[k][c];
        } else if (tid < 192) {
            int c = tid - 128; rkR[c] = R[k][c];
        }
        __syncthreads();
#pragma unroll
        for (int it = 0; it < 16; it++) {
            int e = tid + 512*it;
            int mat = e >> 12;
            int idx = e & 4095;
            int i = idx >> 6, j = idx & 63;
            if (mat == 0) {
                M[i][j] = (i == k) ? rkM[j]*ipv : M[i][j] - fcol[i]*rkM[j];
            } else {
                R[i][j] = (i == k) ? rkR[j]*ipv : R[i][j] - fcol[i]*rkR[j];
            }
        }
        __syncthreads();
    }
    // R = Ad. Write it, then square 3 times (using M as scratch) -> E = Ad^8.
    for (int idx = tid; idx < 64*64; idx += 512)
        d_Ad[layer*4096 + idx] = R[idx >> 6][idx & 63];
    __syncthreads();
    for (int rep = 0; rep < 3; rep++) {
        for (int idx = tid; idx < 4096; idx += 512) {
            int i = idx >> 6, j = idx & 63;
            float acc = 0.f;
#pragma unroll 8
            for (int k = 0; k < 64; k++) acc += R[i][k]*R[k][j];
            M[i][j] = acc;
        }
        __syncthreads();
        for (int idx = tid; idx < 4096; idx += 512)
            R[idx >> 6][idx & 63] = M[idx >> 6][idx & 63];
        __syncthreads();
    }
    for (int idx = tid; idx < 4096; idx += 512)
        d_E[layer*4096 + idx] = R[idx >> 6][idx & 63];
}

// ------- S4 recurrence -> d_k: inline W, then 8 outputs/iter via E = Ad^8 ---
// Clamps are provably inactive (contractive Cayley step, ||x_0|| ~ 0.6).
__global__ void s4_scan_kernel(const float* __restrict__ s4_B,
                               const float* __restrict__ s4_C) {
    int d = blockIdx.x, layer = blockIdx.y;
    int n = threadIdx.x;               // 64 threads
    __shared__ __align__(8) float xs[2][64];
    __shared__ float stage[2][64][9];
    __shared__ float wjs[64];
    // ---- W prologue: w_0 = b; w_{j+1} = Ad^T w_j ----
    float wv[8];
    {
        float adT[64];
#pragma unroll
        for (int m = 0; m < 64; m++) adT[m] = d_Ad[layer*4096 + m*64 + n];
        float w = s4_B[(layer*Nst + n)*Dsz + d];
        wv[0] = w;
        for (int j = 1; j < 8; j++) {
            wjs[n] = w;
            __syncthreads();
            float acc = 0.f;
#pragma unroll
            for (int m = 0; m < 64; m++) acc += adT[m]*wjs[m];
            w = acc;
            wv[j] = w;
            __syncthreads();
        }
    }
    // ---- E load ----
    unsigned long long e2[32];
    const float* Ep = d_E + layer*4096 + n*64;
#pragma unroll
    for (int j = 0; j < 32; j++) {
        float lo = Ep[2*j], hi = Ep[2*j+1];
        unsigned long long v;
        asm("mov.b64 %0, {%1, %2};" : "=l"(v) : "f"(lo), "f"(hi));
        e2[j] = v;
    }
    xs[0][n] = s4_C[(layer*Dsz + d)*Nst + n];
    __syncthreads();
    float* kp = d_k + (layer*Dsz + d)*Tsz;
    int g8 = n >> 3, j8 = n & 7;
    int cur = 0;
    for (int it = 0; it < 125; it++) {
        float x = xs[cur][n];
        int buf = it & 1;
#pragma unroll
        for (int j = 0; j < 8; j++) stage[buf][n][j] = x * wv[j];
        const unsigned long long* xv = reinterpret_cast<const unsigned long long*>(&xs[cur][0]);
        unsigned long long a0 = 0ULL, a1 = 0ULL, a2 = 0ULL, a3 = 0ULL;
#pragma unroll
        for (int j = 0; j < 8; j++) {
            a0 = fma2(e2[j],      xv[j],      a0);
            a1 = fma2(e2[j + 8],  xv[j + 8],  a1);
            a2 = fma2(e2[j + 16], xv[j + 16], a2);
            a3 = fma2(e2[j + 24], xv[j + 24], a3);
        }
        float2 f0 = unpack2(a0), f1 = unpack2(a1), f2 = unpack2(a2), f3 = unpack2(a3);
        float acc = ((f0.x + f0.y) + (f1.x + f1.y)) + ((f2.x + f2.y) + (f3.x + f3.y));
        xs[cur ^ 1][n] = fminf(fmaxf(acc, -100.0f), 100.0f);
        __syncthreads();
        float s = 0.f;
#pragma unroll
        for (int m = 0; m < 8; m++) s += stage[buf][j8 + 8*m][g8];
        s += __shfl_xor_sync(0xffffffffu, s, 4);
        s += __shfl_xor_sync(0xffffffffu, s, 2);
        s += __shfl_xor_sync(0xffffffffu, s, 1);
        if (j8 == 0) {
            int tt = it*8 + g8;
            float ks = fminf(fmaxf(s, -10.0f), 10.0f);
            kp[tt] = ks * expf(-0.01f * (float)tt);
        }
        cur ^= 1;
    }
}

// ---------------- radix-8 butterfly with twiddle ----------------
__device__ __forceinline__ void bf8(C2* v, C2 w1) {
    C2 t0 = cadd(v[0], v[4]), t1 = csub(v[0], v[4]);
    C2 t2 = cadd(v[2], v[6]), t3 = cmulni(csub(v[2], v[6]));
    C2 e0 = cadd(t0, t2), e1 = cadd(t1, t3), e2 = csub(t0, t2), e3 = csub(t1, t3);
    C2 u0 = cadd(v[1], v[5]), u1 = csub(v[1], v[5]);
    C2 u2 = cadd(v[3], v[7]), u3 = cmulni(csub(v[3], v[7]));
    C2 o0 = cadd(u0, u2), o1 = cadd(u1, u3), o2 = csub(u0, u2), o3 = csub(u1, u3);
    const float c = 0.70710678118654752440f;
    C2 q1; q1.x = c*(o1.x + o1.y); q1.y = c*(o1.y - o1.x);
    C2 q2 = cmulni(o2);
    C2 q3; q3.x = c*(o3.y - o3.x); q3.y = -c*(o3.x + o3.y);
    v[0] = cadd(e0, o0); v[1] = cadd(e1, q1); v[2] = cadd(e2, q2); v[3] = cadd(e3, q3);
    v[4] = csub(e0, o0); v[5] = csub(e1, q1); v[6] = csub(e2, q2); v[7] = csub(e3, q3);
    C2 w2 = cmul(w1, w1), w3 = cmul(w2, w1), w4 = cmul(w2, w2);
    C2 w5 = cmul(w4, w1), w6 = cmul(w4, w2), w7 = cmul(w4, w3);
    v[1] = cmul(v[1], w1); v[2] = cmul(v[2], w2); v[3] = cmul(v[3], w3);
    v[4] = cmul(v[4], w4); v[5] = cmul(v[5], w5); v[6] = cmul(v[6], w6); v[7] = cmul(v[7], w7);
}

// radix-8 butterfly with upper 4 inputs == 0 (bit-identical to bf8 on zeros)
__device__ __forceinline__ void bf8h(C2* v, C2 w1) {
    C2 a0 = v[0], a1 = v[1], a2 = v[2], a3 = v[3];
    C2 e0 = cadd(a0, a2);
    C2 e1; e1.x = a0.x + a2.y; e1.y = a0.y - a2.x;   // a0 + (-i)a2
    C2 e2 = csub(a0, a2);
    C2 e3; e3.x = a0.x - a2.y; e3.y = a0.y + a2.x;   // a0 + (i)a2
    C2 o0 = cadd(a1, a3);
    C2 o1; o1.x = a1.x + a3.y; o1.y = a1.y - a3.x;
    C2 o2 = csub(a1, a3);
    C2 o3; o3.x = a1.x - a3.y; o3.y = a1.y + a3.x;
    const float c = 0.70710678118654752440f;
    C2 q1; q1.x = c*(o1.x + o1.y); q1.y = c*(o1.y - o1.x);
    C2 q2 = cmulni(o2);
    C2 q3; q3.x = c*(o3.y - o3.x); q3.y = -c*(o3.x + o3.y);
    v[0] = cadd(e0, o0); v[1] = cadd(e1, q1); v[2] = cadd(e2, q2); v[3] = cadd(e3, q3);
    v[4] = csub(e0, o0); v[5] = csub(e1, q1); v[6] = csub(e2, q2); v[7] = csub(e3, q3);
    C2 w2 = cmul(w1, w1), w3 = cmul(w2, w1), w4 = cmul(w2, w2);
    C2 w5 = cmul(w4, w1), w6 = cmul(w4, w2), w7 = cmul(w4, w3);
    v[1] = cmul(v[1], w1); v[2] = cmul(v[2], w2); v[3] = cmul(v[3], w3);
    v[4] = cmul(v[4], w4); v[5] = cmul(v[5], w5); v[6] = cmul(v[6], w6); v[7] = cmul(v[7], w7);
}

// one Stockham radix-8 stage on float2 buffers
__device__ __forceinline__ void stage8c(const float2* __restrict__ s, float2* __restrict__ d,
                                        const float2* __restrict__ tw,
                                        int p, int q, int st) {
    C2 v[8];
    int base = q + st*p;
#pragma unroll
    for (int k = 0; k < 8; k++) {
        float2 u = s[PDC(base + 256*k)];
        v[k].x = u.x; v[k].y = u.y;
    }
    float2 tv = tw[PDC(p*st)];
    C2 w1; w1.x = tv.x; w1.y = tv.y;
    bf8(v, w1);
    int wb = q + 8*st*p;
#pragma unroll
    for (int k = 0; k < 8; k++)
        d[PDC(wb + st*k)] = make_float2(v[k].x, v[k].y);
}

// shared tail: stages 2,3 + final radix-4 (Q holds stage-1 output)
__device__ __forceinline__ void fft2048c_tail(float2* P, float2* Q,
                                              const float2* __restrict__ tw) {
    int tid = threadIdx.x;
    __syncthreads();
    stage8c(Q, P, tw, tid & 31, tid >> 5, 8); // n=256, s=8
    __syncthreads();
    stage8c(P, Q, tw, tid >> 6, tid & 63, 64);// n=32, s=64
    __syncthreads();
    // radix-4, s=512, no twiddle; 2 butterflies/thread, Q -> P
#pragma unroll
    for (int h = 0; h < 2; h++) {
        int q = tid + 256*h;
        float2 u0 = Q[PDC(q)], u1 = Q[PDC(q + 512)];
        float2 u2 = Q[PDC(q + 1024)], u3 = Q[PDC(q + 1536)];
        C2 x0; x0.x = u0.x; x0.y = u0.y;
        C2 x1; x1.x = u1.x; x1.y = u1.y;
        C2 x2; x2.x = u2.x; x2.y = u2.y;
        C2 x3; x3.x = u3.x; x3.y = u3.y;
        C2 t0 = cadd(x0, x2), t1 = csub(x0, x2);
        C2 t2 = cadd(x1, x3), t3 = cmulni(csub(x1, x3));
        P[PDC(q)]        = make_float2(t0.x + t2.x, t0.y + t2.y);
        P[PDC(q + 512)]  = make_float2(t1.x + t3.x, t1.y + t3.y);
        P[PDC(q + 1024)] = make_float2(t0.x - t2.x, t0.y - t2.y);
        P[PDC(q + 1536)] = make_float2(t1.x - t3.x, t1.y - t3.y);
    }
    __syncthreads();   // result visible
}

// full 2048 FFT (general input): input AND result in P; Q scratch. 256 thr.
__device__ __forceinline__ void fft2048c(float2* P, float2* Q,
                                         const float2* __restrict__ tw) {
    int tid = threadIdx.x;
    __syncthreads();   // input visible
    stage8c(P, Q, tw, tid, 0, 1);             // n=2048, s=1
    fft2048c_tail(P, Q, tw);
}

// forward 2048 FFT for inputs zero on [1024,2048): only P[0,1024) is read.
__device__ __forceinline__ void fft2048c_fwd(float2* P, float2* Q,
                                             const float2* __restrict__ tw) {
    int tid = threadIdx.x;
    __syncthreads();   // input visible
    {
        C2 v[8];
#pragma unroll
        for (int k = 0; k < 4; k++) {
            float2 u = P[PDC(tid + 256*k)];
            v[k].x = u.x; v[k].y = u.y;
        }
        float2 tv = tw[PDC(tid)];
        C2 w1; w1.x = tv.x; w1.y = tv.y;
        bf8h(v, w1);
        int wb = 8*tid;
#pragma unroll
        for (int k = 0; k < 8; k++)
            Q[PDC(wb + k)] = make_float2(v[k].x, v[k].y);
    }
    fft2048c_tail(P, Q, tw);
}

// ---------------- kernel spectra: pack 2 d's per FFT ----------------
// stored K pre-scaled by 0.5 (unpack) * 0.5 (X-unpack fold) * 1/2048 (ifft)
#define KSCL (0.5f/4096.0f)
__global__ void fft_k_kernel() {
    __shared__ float2 A[CBUF], Bc[CBUF];
    __shared__ float2 tws[280];
    int tid = threadIdx.x;
    int dp = blockIdx.x, layer = blockIdx.y;
    int d0 = dp*2, d1 = dp*2 + 1;
    tws[PDC(tid)] = make_float2(d_twr[tid], d_twi[tid]);
    const float* k0 = d_k + (layer*Dsz + d0)*Tsz;
    const float* k1 = d_k + (layer*Dsz + d1)*Tsz;
#pragma unroll
    for (int q = 0; q < 4; q++) {
        int t = tid + 256*q;
        float v0 = (t < Tsz) ? k0[t] : 0.0f;
        float v1 = (t < Tsz) ? k1[t] : 0.0f;
        A[PDC(t)] = make_float2(v0, v1);
    }
    fft2048c_fwd(A, Bc, tws);
    float2* K0 = d_kf + (layer*Dsz + d0)*FFTN;
    float2* K1 = d_kf + (layer*Dsz + d1)*FFTN;
#pragma unroll
    for (int q = 0; q < 8; q++) {
        int f = tid + 256*q;
        int fm = (FFTN - f) & (FFTN - 1);
        float2 Zf = A[PDC(f)];
        float2 Zm = A[PDC(fm)];
        K0[f] = make_float2(KSCL*(Zf.x + Zm.x), KSCL*(Zf.y - Zm.y));
        K1[f] = make_float2(KSCL*(Zf.y + Zm.y), KSCL*(Zm.x - Zf.x));
    }
}

// ---- input projection + LN + pos-enc + L2-normalize -> d_xt2 (B,D,T) -------
// 128 threads; each owns 2 d's (tid, tid+128); x tile staged as float2 pairs.
__global__ void in_proj_ln_kernel(const float* __restrict__ x,
                                  const float* __restrict__ b_in,
                                  const float* __restrict__ g,
                                  const float* __restrict__ bbp) {
    int b = blockIdx.x, t0 = blockIdx.y * 20;
    int tid = threadIdx.x;          // 128
    int lane = tid & 31, w = tid >> 5;   // 4 warps
    int d0 = tid, d1 = tid + 128;
    __shared__ float ws[32][256];
    __shared__ __align__(8) float2 xs2[32][10];
    __shared__ float red1[4][20], red2[4][20];
    __shared__ float msh[20], ish[20];
    float acc0[20], acc1[20];
#pragma unroll
    for (int j = 0; j < 20; j++) { acc0[j] = 0.0f; acc1[j] = 0.0f; }
    for (int c0 = 0; c0 < Csz; c0 += 32) {
        __syncthreads();
        for (int l = tid; l < 32*256; l += 128) {
            int i = l >> 8, col = l & 255;
            ws[i][col] = (c0 + i < Csz) ? d_wt[(c0 + i)*Dsz + col] : 0.0f;
        }
        // x rows are float2-aligned: base (b*Csz+cc)*Tsz + t0, both even
        for (int l = tid; l < 320; l += 128) {
            int cc = l / 10, jp = l % 10;
            xs2[cc][jp] = (c0 + cc < Csz)
                ? *reinterpret_cast<const float2*>(x + (b*Csz + c0 + cc)*Tsz + t0 + 2*jp)
                : make_float2(0.f, 0.f);
        }
        __syncthreads();
#pragma unroll 4
        for (int cc = 0; cc < 32; cc++) {
            float w0 = ws[cc][d0];
            float w1 = ws[cc][d1];
#pragma unroll
            for (int jp = 0; jp < 10; jp++) {
                float2 xv = xs2[cc][jp];
                acc0[2*jp]   += w0 * xv.x;
                acc0[2*jp+1] += w0 * xv.y;
                acc1[2*jp]   += w1 * xv.x;
                acc1[2*jp+1] += w1 * xv.y;
            }
        }
    }
    float bias0 = b_in[d0], bias1 = b_in[d1];
#pragma unroll
    for (int j = 0; j < 20; j++) { acc0[j] += bias0; acc1[j] += bias1; }
    // block reduction 1: mean / var per t
#pragma unroll
    for (int j = 0; j < 20; j++) {
        float sv = acc0[j] + acc1[j];
        float sq = acc0[j]*acc0[j] + acc1[j]*acc1[j];
#pragma unroll
        for (int off = 16; off; off >>= 1) {
            sv += __shfl_xor_sync(0xffffffffu, sv, off);
            sq += __shfl_xor_sync(0xffffffffu, sq, off);
        }
        if (lane == 0) { red1[w][j] = sv; red2[w][j] = sq; }
    }
    __syncthreads();
    if (tid < 20) {
        float S = 0.f, Q = 0.f;
        for (int ww = 0; ww < 4; ww++) { S += red1[ww][tid]; Q += red2[ww][tid]; }
        float m = S * (1.0f/256.0f);
        float var = Q * (1.0f/256.0f) - m*m;
        msh[tid] = m; ish[tid] = rsqrtf(var + 1e-5f);
    }
    __syncthreads();
    float g0 = g[d0], g1 = g[d1], bv0 = bbp[d0], bv1 = bbp[d1];
#pragma unroll
    for (int j = 0; j < 20; j++) {
        float m = msh[j], is = ish[j];
        acc0[j] = (acc0[j] - m)*is*g0 + bv0 + d_pe[(t0 + j)*Dsz + d0];
        acc1[j] = (acc1[j] - m)*is*g1 + bv1 + d_pe[(t0 + j)*Dsz + d1];
    }
    // block reduction 2: L2 norm per t
#pragma unroll
    for (int j = 0; j < 20; j++) {
        float sq = acc0[j]*acc0[j] + acc1[j]*acc1[j];
#pragma unroll
        for (int off = 16; off; off >>= 1)
            sq += __shfl_xor_sync(0xffffffffu, sq, off);
        if (lane == 0) red1[w][j] = sq;
    }
    __syncthreads();
    if (tid < 20) {
        float Q = 0.f;
        for (int ww = 0; ww < 4; ww++) Q += red1[ww][tid];
        float nrm = sqrtf(Q) + 1e-8f;
        d_nrm[b*Tsz + t0 + tid] = nrm;
        ish[tid] = 1.0f / nrm;
    }
    __syncthreads();
#pragma unroll
    for (int j = 0; j < 20; j++) { acc0[j] *= ish[j]; acc1[j] *= ish[j]; }
    float4* op0 = reinterpret_cast<float4*>(d_xt2 + ((size_t)b*Dsz + d0)*Tsz + t0);
    float4* op1 = reinterpret_cast<float4*>(d_xt2 + ((size_t)b*Dsz + d1)*Tsz + t0);
#pragma unroll
    for (int q = 0; q < 5; q++) {
        op0[q] = make_float4(acc0[4*q], acc0[4*q+1], acc0[4*q+2], acc0[4*q+3]);
        op1[q] = make_float4(acc1[4*q], acc1[4*q+1], acc1[4*q+2], acc1[4*q+3]);
    }
}

// -------- FFT conv + gate + gelu + residual (z = gelu(y)+1.1h), in-place ----
// Thread owns t in [4*tid, 4*tid+4): tid<250 exactly covers Tsz=1000.
__global__ void fft_conv_kernel(int layer, const float* __restrict__ s4_D) {
    __shared__ float2 A[CBUF], Bc[CBUF];
    __shared__ float2 tws[280];
    int tid = threadIdx.x;
    int b = blockIdx.x, dp = blockIdx.y;
    int d0 = dp*2, d1 = dp*2 + 1;
    tws[PDC(tid)] = make_float2(d_twr[tid], d_twi[tid]);
    float* x0 = d_xt2 + ((size_t)b*Dsz + d0)*Tsz;
    float* x1 = d_xt2 + ((size_t)b*Dsz + d1)*Tsz;
    const float* np = d_nrm + b*Tsz;
    int t4 = tid * 4;
    bool valid = (t4 < Tsz);
    float4 fx0, fx1, fnr;
    if (valid) {
        fx0 = *reinterpret_cast<const float4*>(x0 + t4);
        fx1 = *reinterpret_cast<const float4*>(x1 + t4);
        fnr = *reinterpret_cast<const float4*>(np + t4);
    } else {
        fx0 = make_float4(0.f,0.f,0.f,0.f);
        fx1 = fx0; fnr = fx0;
    }
    // stage input into [0,1024) only; fwd FFT never reads the upper half
    if (t4 < 1024) {
        A[PDC(t4 + 0)] = make_float2(fx0.x, fx1.x);
        A[PDC(t4 + 1)] = make_float2(fx0.y, fx1.y);
        A[PDC(t4 + 2)] = make_float2(fx0.z, fx1.z);
        A[PDC(t4 + 3)] = make_float2(fx0.w, fx1.w);
    }
    fft2048c_fwd(A, Bc, tws);   // Z in A
    const float2* K0 = d_kf + (layer*Dsz + d0)*FFTN;
    const float2* K1 = d_kf + (layer*Dsz + d1)*FFTN;
    // spectral multiply with conjugate symmetry: f in [0,1024), dual write
#pragma unroll
    for (int q = 0; q < 4; q++) {
        int f = tid + 256*q;
        int fm = (FFTN - f) & (FFTN - 1);
        float2 Zf = A[PDC(f)];
        float2 Zm = A[PDC(fm)];
        C2 X0; X0.x = Zf.x + Zm.x; X0.y = Zf.y - Zm.y;
        C2 X1; X1.x = Zf.y + Zm.y; X1.y = Zm.x - Zf.x;
        float2 k0 = K0[f], k1 = K1[f];
        C2 c0; c0.x = k0.x; c0.y = k0.y;
        C2 c1; c1.x = k1.x; c1.y = k1.y;
        C2 Y0 = cmul(X0, c0);
        C2 Y1 = cmul(X1, c1);
        Bc[PDC(f)]  = make_float2(Y0.x - Y1.y, -(Y0.y + Y1.x));  // conj(S)(f)
        Bc[PDC(fm)] = make_float2(Y0.x + Y1.y,   Y0.y - Y1.x);   // conj(S)(fm)
    }
    if (tid == 0) {   // self-conjugate bin f = 1024
        float2 Zf = A[PDC(1024)];
        C2 X0; X0.x = 2.0f*Zf.x; X0.y = 0.0f;
        C2 X1; X1.x = 2.0f*Zf.y; X1.y = 0.0f;
        float2 k0 = K0[1024], k1 = K1[1024];
        C2 c0; c0.x = k0.x; c0.y = k0.y;
        C2 c1; c1.x = k1.x; c1.y = k1.y;
        C2 Y0 = cmul(X0, c0);
        C2 Y1 = cmul(X1, c1);
        Bc[PDC(1024)] = make_float2(Y0.x - Y1.y, -(Y0.y + Y1.x));
    }
    fft2048c(Bc, A, tws);   // V in Bc (scale folded into K); ifft = conj(V)
    float gate0 = 1.0f / (1.0f + __expf(-s4_D[layer*Dsz + d0]));
    float gate1 = 1.0f / (1.0f + __expf(-s4_D[layer*Dsz + d1]));
    if (valid) {
        float2 V0 = Bc[PDC(t4 + 0)];
        float2 V1 = Bc[PDC(t4 + 1)];
        float2 V2 = Bc[PDC(t4 + 2)];
        float2 V3 = Bc[PDC(t4 + 3)];
        float4 r0, r1;
        {
            float y0 =  V0.x + fx0.x*gate0, y1 = -V0.y + fx1.x*gate1;
            r0.x = 0.5f*y0*(1.0f + erff(y0*0.70710678118654752f)) + 1.1f*fx0.x*fnr.x;
            r1.x = 0.5f*y1*(1.0f + erff(y1*0.70710678118654752f)) + 1.1f*fx1.x*fnr.x;
        }
        {
            float y0 =  V1.x + fx0.y*gate0, y1 = -V1.y + fx1.y*gate1;
            r0.y = 0.5f*y0*(1.0f + erff(y0*0.70710678118654752f)) + 1.1f*fx0.y*fnr.y;
            r1.y = 0.5f*y1*(1.0f + erff(y1*0.70710678118654752f)) + 1.1f*fx1.y*fnr.y;
        }
        {
            float y0 =  V2.x + fx0.z*gate0, y1 = -V2.y + fx1.z*gate1;
            r0.z = 0.5f*y0*(1.0f + erff(y0*0.70710678118654752f)) + 1.1f*fx0.z*fnr.z;
            r1.z = 0.5f*y1*(1.0f + erff(y1*0.70710678118654752f)) + 1.1f*fx1.z*fnr.z;
        }
        {
            float y0 =  V3.x + fx0.w*gate0, y1 = -V3.y + fx1.w*gate1;
            r0.w = 0.5f*y0*(1.0f + erff(y0*0.70710678118654752f)) + 1.1f*fx0.w*fnr.w;
            r1.w = 0.5f*y1*(1.0f + erff(y1*0.70710678118654752f)) + 1.1f*fx1.w*fnr.w;
        }
        *reinterpret_cast<float4*>(x0 + t4) = r0;
        *reinterpret_cast<float4*>(x1 + t4) = r1;
    }
}

// ---- post: LN(z); last -> d_h (B,T,D); else normalized transposed + norms --
__global__ void post_ln_norm_t_kernel(int layer, int last,
                                      const float* __restrict__ ln_g,
                                      const float* __restrict__ ln_b) {
    __shared__ float tile[32][257];
    int b = blockIdx.x, t0 = blockIdx.y * 32;
    int tid = threadIdx.x, lane = tid & 31, w = tid >> 5;
#pragma unroll
    for (int i = 0; i < 32; i++) {
        int dd = i*8 + w;
        int t = t0 + lane;
        tile[lane][dd] = (t < Tsz) ? d_xt2[((size_t)b*Dsz + dd)*Tsz + t] : 0.0f;
    }
    __syncthreads();
    const float* g  = ln_g + layer*Dsz;
    const float* bb = ln_b + layer*Dsz;
#pragma unroll
    for (int j = 0; j < 4; j++) {
        int r = w + 8*j;
        int t = t0 + r;
        if (t >= Tsz) continue;
        float z[8]; float s = 0.f, s2 = 0.f;
#pragma unroll
        for (int k = 0; k < 8; k++) {
            float zz = tile[r][lane + 32*k];
            z[k] = zz; s += zz; s2 += zz*zz;
        }
#pragma unroll
        for (int off = 16; off; off >>= 1) {
            s  += __shfl_xor_sync(0xffffffffu, s,  off);
            s2 += __shfl_xor_sync(0xffffffffu, s2, off);
        }
        float m = s * (1.0f/256.0f);
        float var = s2 * (1.0f/256.0f) - m*m;
        float is = rsqrtf(var + 1e-5f);
        if (last) {
            float* hp = d_h + ((size_t)b*Tsz + t)*Dsz;
#pragma unroll
            for (int k = 0; k < 8; k++) {
                int dd = lane + 32*k;
                hp[dd] = (z[k] - m)*is*g[dd] + bb[dd];
            }
        } else {
            float o[8]; float ss = 0.f;
#pragma unroll
            for (int k = 0; k < 8; k++) {
                int dd = lane + 32*k;
                float ov = (z[k] - m)*is*g[dd] + bb[dd];
                o[k] = ov; ss += ov*ov;
            }
#pragma unroll
            for (int off = 16; off; off >>= 1) ss += __shfl_xor_sync(0xffffffffu, ss, off);
            float nrm = sqrtf(ss) + 1e-8f;
            float invn = 1.0f / nrm;
            if (lane == 0) d_nrm[b*Tsz + t] = nrm;
#pragma unroll
            for (int k = 0; k < 8; k++) tile[r][lane + 32*k] = o[k]*invn;
        }
    }
    if (last) return;
    __syncthreads();
#pragma unroll
    for (int i = 0; i < 32; i++) {
        int dd = i*8 + w;
        int t = t0 + lane;
        if (t < Tsz) d_xt2[((size_t)b*Dsz + dd)*Tsz + t] = tile[lane][dd];
    }
}

// ---------------- fused MHA pooling + head ----------------
__global__ void pool_head_kernel(const float* __restrict__ cls,
                                 const float* __restrict__ in_w,
                                 const float* __restrict__ in_b,
                                 const float* __restrict__ out_w,
                                 const float* __restrict__ out_b,
                                 const float* __restrict__ hw1,
                                 const float* __restrict__ hb1,
                                 const float* __restrict__ hw2,
                                 const float* __restrict__ hb2,
                                 float* __restrict__ out) {
    int b = blockIdx.x;
    int tid = threadIdx.x, lane = tid & 31, w = tid >> 5;
    __shared__ float Q[256];
    __shared__ float vp[8][256];
    __shared__ float sc[8][1001];
    __shared__ float ch[8];
    __shared__ float red[256];
    __shared__ float hsm[128];

    {
        float acc = in_b[tid];
        for (int c = 0; c < 256; c++) acc += cls[c] * in_w[tid*256 + c];
        Q[tid] = acc;
    }
    __syncthreads();
#pragma unroll
    for (int h = 0; h < 8; h++) {
        float acc = 0.f;
#pragma unroll
        for (int i = 0; i < 32; i++)
            acc += in_w[(256 + h*32 + i)*256 + tid] * Q[h*32 + i];
        vp[h][tid] = acc;
    }
    if (tid < 8) {
        float acc = 0.f;
        for (int i = 0; i < 32; i++) acc += in_b[256 + tid*32 + i] * Q[tid*32 + i];
        ch[tid] = acc;
    }
    __syncthreads();
    const float iss = 0.17677669529663687f; // 1/sqrt(32)
    for (int s = w; s < 1001; s += 8) {
        const float* kvr = (s == 0) ? cls : (d_h + ((size_t)b*Tsz + s - 1)*Dsz);
        float xv[8];
#pragma unroll
        for (int k = 0; k < 8; k++) xv[k] = kvr[lane*8 + k];
#pragma unroll
        for (int h = 0; h < 8; h++) {
            float a = 0.f;
#pragma unroll
            for (int k = 0; k < 8; k++) a += xv[k] * vp[h][lane*8 + k];
#pragma unroll
            for (int off = 16; off; off >>= 1) a += __shfl_xor_sync(0xffffffffu, a, off);
            if (lane == h) sc[h][s] = (a + ch[h]) * iss;
        }
    }
    __syncthreads();
    {
        int h = w;
        float mx = -1e30f;
        for (int s = lane; s < 1001; s += 32) mx = fmaxf(mx, sc[h][s]);
#pragma unroll
        for (int off = 16; off; off >>= 1) mx = fmaxf(mx, __shfl_xor_sync(0xffffffffu, mx, off));
        float sum = 0.f;
        for (int s = lane; s < 1001; s += 32) { float e = expf(sc[h][s] - mx); sc[h][s] = e; sum += e; }
#pragma unroll
        for (int off = 16; off; off >>= 1) sum += __shfl_xor_sync(0xffffffffu, sum, off);
        float invs = 1.0f / sum;
        for (int s = lane; s < 1001; s += 32) sc[h][s] *= invs;
    }
    __syncthreads();
    float pj[8];
#pragma unroll
    for (int h = 0; h < 8; h++) pj[h] = 0.f;
    for (int s = 0; s < 1001; s++) {
        float kvv = (s == 0) ? cls[tid] : d_h[((size_t)b*Tsz + s - 1)*Dsz + tid];
#pragma unroll
        for (int h = 0; h < 8; h++) pj[h] += sc[h][s] * kvv;
    }
    __syncthreads();
#pragma unroll
    for (int h = 0; h < 8; h++) vp[h][tid] = pj[h];
    __syncthreads();
    {
        int h = tid >> 5;
        float acc = in_b[512 + tid];
        for (int j = 0; j < 256; j++) acc += in_w[(512 + tid)*256 + j] * vp[h][j];
        Q[tid] = acc;
    }
    __syncthreads();
    {
        float acc = out_b[tid];
        for (int i = 0; i < 256; i++) acc += out_w[tid*256 + i] * Q[i];
        red[tid] = acc;
    }
    __syncthreads();
    if (tid < 128) {
        float acc = hb1[tid];
        for (int i = 0; i < 256; i++) acc += hw1[tid*256 + i] * red[i];
        hsm[tid] = fmaxf(acc, 0.0f);
    }
    __syncthreads();
    if (w == 0) {
        float a = 0.f;
#pragma unroll
        for (int k = 0; k < 4; k++) a += hsm[lane + 32*k] * hw2[lane + 32*k];
#pragma unroll
        for (int off = 16; off; off >>= 1) a += __shfl_xor_sync(0xffffffffu, a, off);
        if (lane == 0) out[b] = a + hb2[0];
    }
}

// ---------------- launch ----------------
extern "C" void kernel_launch(void* const* d_in, const int* in_sizes, int n_in,
                              void* d_out, int out_size) {
    const float* x        = (const float*)d_in[0];
    const float* w_in     = (const float*)d_in[1];
    const float* b_in     = (const float*)d_in[2];
    const float* ln_in_g  = (const float*)d_in[3];
    const float* ln_in_b  = (const float*)d_in[4];
    const float* s4_B     = (const float*)d_in[5];
    const float* s4_C     = (const float*)d_in[6];
    const float* s4_logdt = (const float*)d_in[7];
    const float* s4_D     = (const float*)d_in[8];
    const float* ln_g     = (const float*)d_in[9];
    const float* ln_b     = (const float*)d_in[10];
    const float* cls      = (const float*)d_in[11];
    const float* mha_in_w = (const float*)d_in[12];
    const float* mha_in_b = (const float*)d_in[13];
    const float* mha_out_w= (const float*)d_in[14];
    const float* mha_out_b= (const float*)d_in[15];
    const float* head_w1  = (const float*)d_in[16];
    const float* head_b1  = (const float*)d_in[17];
    const float* head_w2  = (const float*)d_in[18];
    const float* head_b2  = (const float*)d_in[19];
    float* out = (float*)d_out;

    setup_kernel<<<256, 256>>>(w_in);
    compute_AdE_kernel<<<NL, 512>>>(s4_logdt);
    s4_scan_kernel<<<dim3(Dsz, NL), 64>>>(s4_B, s4_C);
    fft_k_kernel<<<dim3(Dsz/2, NL), 256>>>();
    in_proj_ln_kernel<<<dim3(Bsz, 50), 128>>>(x, b_in, ln_in_g, ln_in_b);
    for (int layer = 0; layer < NL; layer++) {
        fft_conv_kernel<<<dim3(Bsz, Dsz/2), 256>>>(layer, s4_D);
        post_ln_norm_t_kernel<<<dim3(Bsz, 32), 256>>>(layer, (layer == NL-1) ? 1 : 0, ln_g, ln_b);
    }
    pool_head_kernel<<<Bsz, 256>>>(cls, mha_in_w, mha_in_b, mha_out_w, mha_out_b,
                                   head_w1, head_b1, head_w2, head_b2, out);
}

// round 17
// speedup vs baseline: 1.0399x; 1.0262x over previous
#include <cuda_runtime.h>
#include <cuda_bf16.h>
#include <math.h>

#define Bsz 32
#define Csz 129
#define Tsz 1000
#define Dsz 256
#define Nst 64
#define NL  4
#define FFTN 2048

// ---------------- scratch (device globals; no runtime alloc) ----------------
__device__ float  d_h [Bsz*Tsz*Dsz];     // final hidden (B,T,D) for pooling
__device__ float  d_xt2[Bsz*Tsz*Dsz];    // (B,D,T): normalized x OR conv z, in-place
__device__ float  d_nrm[Bsz*Tsz];        // per (b,t) L2 norm of LN output
__device__ float  d_k [NL*Dsz*Tsz];      // S4 kernels
__device__ float2 d_kf[NL*Dsz*FFTN];     // spectra of kernels (pre-scaled by 0.5/4096)
__device__ float  d_Ad[NL*Nst*Nst];
__device__ float  d_E [NL*Nst*Nst];      // Ad^8
__device__ float  d_twr[256];
__device__ float  d_twi[256];
__device__ float  d_wt[Csz*Dsz];         // transposed w_in
__device__ float  d_pe[Tsz*Dsz];         // positional encoding table

#define PI_D 3.14159265358979323846

// ---------------- complex helpers ----------------
struct C2 { float x, y; };
__device__ __forceinline__ C2 cmul(C2 a, C2 b){ C2 r; r.x = a.x*b.x - a.y*b.y; r.y = a.x*b.y + a.y*b.x; return r; }
__device__ __forceinline__ C2 cadd(C2 a, C2 b){ C2 r; r.x = a.x+b.x; r.y = a.y+b.y; return r; }
__device__ __forceinline__ C2 csub(C2 a, C2 b){ C2 r; r.x = a.x-b.x; r.y = a.y-b.y; return r; }
__device__ __forceinline__ C2 cmulni(C2 a){ C2 r; r.x = a.y; r.y = -a.x; return r; }  // a * (-i)

// padded complex (float2) smem index: conflict-free for strides 1/8/64
#define PDC(i) ((i) + ((i)>>4) + ((i)>>8))
#define CBUF 2200

// ---------------- f32x2 packed fma ----------------
__device__ __forceinline__ unsigned long long fma2(unsigned long long a, unsigned long long b, unsigned long long c){
    unsigned long long d;
    asm("fma.rn.f32x2 %0, %1, %2, %3;" : "=l"(d) : "l"(a), "l"(b), "l"(c));
    return d;
}
__device__ __forceinline__ float2 unpack2(unsigned long long v){
    float2 r; asm("mov.b64 {%0, %1}, %2;" : "=f"(r.x), "=f"(r.y) : "l"(v)); return r;
}

// ---------------- setup: twiddles, w transpose, pos-encoding ----------------
__global__ void setup_kernel(const float* __restrict__ w_in) {
    int idx = blockIdx.x * blockDim.x + threadIdx.x;
    int stride = gridDim.x * blockDim.x;
    if (idx < 256) {
        double ang = -2.0 * PI_D * (double)idx / (double)FFTN;
        d_twr[idx] = (float)cos(ang);
        d_twi[idx] = (float)sin(ang);
    }
    for (int i = idx; i < Csz*Dsz; i += stride) {
        int dd = i / Csz, c = i % Csz;
        d_wt[c*Dsz + dd] = w_in[i];
    }
    for (int i = idx; i < Tsz*Dsz; i += stride) {
        int t = i / Dsz, dd = i % Dsz;
        double divv = exp(-(double)(dd >> 1) * 2.0 * log(10000.0) / (double)Dsz);
        double arg = (double)t * divv;
        d_pe[i] = (float)((dd & 1) ? cos(arg) : sin(arg));
    }
}

// ---- Ad = solve(I - dtA, I + dtA) (pivot-free GJ) + E = Ad^8 (3 squarings) --
__global__ void compute_AdE_kernel(const float* __restrict__ s4_logdt) {
    int layer = blockIdx.x;
    __shared__ float M[64][65];
    __shared__ float R[64][65];
    __shared__ float fcol[64];
    __shared__ float rkM[64];
    __shared__ float rkR[64];
    int tid = threadIdx.x; // 512 threads

    float logdt = s4_logdt[layer*Dsz + 0];
    float dt = fminf(fmaxf(expf(logdt), 1e-4f), 0.1f);
    float hdt = dt * 0.5f;

    for (int idx = tid; idx < 64*64; idx += 512) {
        int i = idx >> 6, j = idx & 63;
        float Pi = sqrtf(1.0f + 2.0f*i), Pj = sqrtf(1.0f + 2.0f*j);
        float a;
        if (i == j)      a = -((float)i + 0.5f);
        else if (i > j)  a = -Pi*Pj;
        else             a =  Pi*Pj;
        float eye = (i == j) ? 1.0f : 0.0f;
        M[i][j] = eye - hdt*a;
        R[i][j] = eye + hdt*a;
    }
    __syncthreads();

    for (int k = 0; k < 64; k++) {
        float ipv = 1.0f / M[k][k];
        if (tid < 64) {
            fcol[tid] = (tid == k) ? 0.0f : M[tid][k] * ipv;
        } else if (tid < 128) {
            int c = tid - 64; rkM[c] = M[k][c];
        } else if (tid < 192) {
            int c = tid - 128; rkR[c] = R[k][c];
        }
        __syncthreads();
#pragma unroll
        for (int it = 0; it < 16; it++) {
            int e = tid + 512*it;
            int mat = e >> 12;
            int idx = e & 4095;
            int i = idx >> 6, j = idx & 63;
            if (mat == 0) {
                M[i][j] = (i == k) ? rkM[j]*ipv : M[i][j] - fcol[i]*rkM[j];
            } else {
                R[i][j] = (i == k) ? rkR[j]*ipv : R[i][j] - fcol[i]*rkR[j];
            }
        }
        __syncthreads();
    }
    // R = Ad. Write it, then square 3 times (using M as scratch) -> E = Ad^8.
    for (int idx = tid; idx < 64*64; idx += 512)
        d_Ad[layer*4096 + idx] = R[idx >> 6][idx & 63];
    __syncthreads();
    for (int rep = 0; rep < 3; rep++) {
        for (int idx = tid; idx < 4096; idx += 512) {
            int i = idx >> 6, j = idx & 63;
            float acc = 0.f;
#pragma unroll 8
            for (int k = 0; k < 64; k++) acc += R[i][k]*R[k][j];
            M[i][j] = acc;
        }
        __syncthreads();
        for (int idx = tid; idx < 4096; idx += 512)
            R[idx >> 6][idx & 63] = M[idx >> 6][idx & 63];
        __syncthreads();
    }
    for (int idx = tid; idx < 4096; idx += 512)
        d_E[layer*4096 + idx] = R[idx >> 6][idx & 63];
}

// ------- S4 recurrence -> d_k: inline W, then 8 outputs/iter via E = Ad^8 ---
// Clamps are provably inactive (contractive Cayley step, ||x_0|| ~ 0.6).
__global__ void s4_scan_kernel(const float* __restrict__ s4_B,
                               const float* __restrict__ s4_C) {
    int d = blockIdx.x, layer = blockIdx.y;
    int n = threadIdx.x;               // 64 threads
    __shared__ __align__(8) float xs[2][64];
    __shared__ float stage[2][64][9];
    __shared__ float wjs[64];
    // ---- W prologue: w_0 = b; w_{j+1} = Ad^T w_j ----
    float wv[8];
    {
        float adT[64];
#pragma unroll
        for (int m = 0; m < 64; m++) adT[m] = d_Ad[layer*4096 + m*64 + n];
        float w = s4_B[(layer*Nst + n)*Dsz + d];
        wv[0] = w;
        for (int j = 1; j < 8; j++) {
            wjs[n] = w;
            __syncthreads();
            float acc = 0.f;
#pragma unroll
            for (int m = 0; m < 64; m++) acc += adT[m]*wjs[m];
            w = acc;
            wv[j] = w;
            __syncthreads();
        }
    }
    // ---- E load ----
    unsigned long long e2[32];
    const float* Ep = d_E + layer*4096 + n*64;
#pragma unroll
    for (int j = 0; j < 32; j++) {
        float lo = Ep[2*j], hi = Ep[2*j+1];
        unsigned long long v;
        asm("mov.b64 %0, {%1, %2};" : "=l"(v) : "f"(lo), "f"(hi));
        e2[j] = v;
    }
    xs[0][n] = s4_C[(layer*Dsz + d)*Nst + n];
    __syncthreads();
    float* kp = d_k + (layer*Dsz + d)*Tsz;
    int g8 = n >> 3, j8 = n & 7;
    int cur = 0;
    for (int it = 0; it < 125; it++) {
        float x = xs[cur][n];
        int buf = it & 1;
#pragma unroll
        for (int j = 0; j < 8; j++) stage[buf][n][j] = x * wv[j];
        const unsigned long long* xv = reinterpret_cast<const unsigned long long*>(&xs[cur][0]);
        unsigned long long a0 = 0ULL, a1 = 0ULL, a2 = 0ULL, a3 = 0ULL;
#pragma unroll
        for (int j = 0; j < 8; j++) {
            a0 = fma2(e2[j],      xv[j],      a0);
            a1 = fma2(e2[j + 8],  xv[j + 8],  a1);
            a2 = fma2(e2[j + 16], xv[j + 16], a2);
            a3 = fma2(e2[j + 24], xv[j + 24], a3);
        }
        float2 f0 = unpack2(a0), f1 = unpack2(a1), f2 = unpack2(a2), f3 = unpack2(a3);
        float acc = ((f0.x + f0.y) + (f1.x + f1.y)) + ((f2.x + f2.y) + (f3.x + f3.y));
        xs[cur ^ 1][n] = fminf(fmaxf(acc, -100.0f), 100.0f);
        __syncthreads();
        float s = 0.f;
#pragma unroll
        for (int m = 0; m < 8; m++) s += stage[buf][j8 + 8*m][g8];
        s += __shfl_xor_sync(0xffffffffu, s, 4);
        s += __shfl_xor_sync(0xffffffffu, s, 2);
        s += __shfl_xor_sync(0xffffffffu, s, 1);
        if (j8 == 0) {
            int tt = it*8 + g8;
            float ks = fminf(fmaxf(s, -10.0f), 10.0f);
            kp[tt] = ks * expf(-0.01f * (float)tt);
        }
        cur ^= 1;
    }
}

// ---------------- radix-8 butterfly with twiddle ----------------
__device__ __forceinline__ void bf8(C2* v, C2 w1) {
    C2 t0 = cadd(v[0], v[4]), t1 = csub(v[0], v[4]);
    C2 t2 = cadd(v[2], v[6]), t3 = cmulni(csub(v[2], v[6]));
    C2 e0 = cadd(t0, t2), e1 = cadd(t1, t3), e2 = csub(t0, t2), e3 = csub(t1, t3);
    C2 u0 = cadd(v[1], v[5]), u1 = csub(v[1], v[5]);
    C2 u2 = cadd(v[3], v[7]), u3 = cmulni(csub(v[3], v[7]));
    C2 o0 = cadd(u0, u2), o1 = cadd(u1, u3), o2 = csub(u0, u2), o3 = csub(u1, u3);
    const float c = 0.70710678118654752440f;
    C2 q1; q1.x = c*(o1.x + o1.y); q1.y = c*(o1.y - o1.x);
    C2 q2 = cmulni(o2);
    C2 q3; q3.x = c*(o3.y - o3.x); q3.y = -c*(o3.x + o3.y);
    v[0] = cadd(e0, o0); v[1] = cadd(e1, q1); v[2] = cadd(e2, q2); v[3] = cadd(e3, q3);
    v[4] = csub(e0, o0); v[5] = csub(e1, q1); v[6] = csub(e2, q2); v[7] = csub(e3, q3);
    C2 w2 = cmul(w1, w1), w3 = cmul(w2, w1), w4 = cmul(w2, w2);
    C2 w5 = cmul(w4, w1), w6 = cmul(w4, w2), w7 = cmul(w4, w3);
    v[1] = cmul(v[1], w1); v[2] = cmul(v[2], w2); v[3] = cmul(v[3], w3);
    v[4] = cmul(v[4], w4); v[5] = cmul(v[5], w5); v[6] = cmul(v[6], w6); v[7] = cmul(v[7], w7);
}

// radix-8 butterfly with upper 4 inputs == 0 (bit-identical to bf8 on zeros)
__device__ __forceinline__ void bf8h(C2* v, C2 w1) {
    C2 a0 = v[0], a1 = v[1], a2 = v[2], a3 = v[3];
    C2 e0 = cadd(a0, a2);
    C2 e1; e1.x = a0.x + a2.y; e1.y = a0.y - a2.x;   // a0 + (-i)a2
    C2 e2 = csub(a0, a2);
    C2 e3; e3.x = a0.x - a2.y; e3.y = a0.y + a2.x;   // a0 + (i)a2
    C2 o0 = cadd(a1, a3);
    C2 o1; o1.x = a1.x + a3.y; o1.y = a1.y - a3.x;
    C2 o2 = csub(a1, a3);
    C2 o3; o3.x = a1.x - a3.y; o3.y = a1.y + a3.x;
    const float c = 0.70710678118654752440f;
    C2 q1; q1.x = c*(o1.x + o1.y); q1.y = c*(o1.y - o1.x);
    C2 q2 = cmulni(o2);
    C2 q3; q3.x = c*(o3.y - o3.x); q3.y = -c*(o3.x + o3.y);
    v[0] = cadd(e0, o0); v[1] = cadd(e1, q1); v[2] = cadd(e2, q2); v[3] = cadd(e3, q3);
    v[4] = csub(e0, o0); v[5] = csub(e1, q1); v[6] = csub(e2, q2); v[7] = csub(e3, q3);
    C2 w2 = cmul(w1, w1), w3 = cmul(w2, w1), w4 = cmul(w2, w2);
    C2 w5 = cmul(w4, w1), w6 = cmul(w4, w2), w7 = cmul(w4, w3);
    v[1] = cmul(v[1], w1); v[2] = cmul(v[2], w2); v[3] = cmul(v[3], w3);
    v[4] = cmul(v[4], w4); v[5] = cmul(v[5], w5); v[6] = cmul(v[6], w6); v[7] = cmul(v[7], w7);
}

// one Stockham radix-8 stage on float2 buffers
__device__ __forceinline__ void stage8c(const float2* __restrict__ s, float2* __restrict__ d,
                                        const float2* __restrict__ tw,
                                        int p, int q, int st) {
    C2 v[8];
    int base = q + st*p;
#pragma unroll
    for (int k = 0; k < 8; k++) {
        float2 u = s[PDC(base + 256*k)];
        v[k].x = u.x; v[k].y = u.y;
    }
    float2 tv = tw[PDC(p*st)];
    C2 w1; w1.x = tv.x; w1.y = tv.y;
    bf8(v, w1);
    int wb = q + 8*st*p;
#pragma unroll
    for (int k = 0; k < 8; k++)
        d[PDC(wb + st*k)] = make_float2(v[k].x, v[k].y);
}

// shared tail: stages 2,3 + final radix-4 (Q holds stage-1 output)
__device__ __forceinline__ void fft2048c_tail(float2* P, float2* Q,
                                              const float2* __restrict__ tw) {
    int tid = threadIdx.x;
    __syncthreads();
    stage8c(Q, P, tw, tid & 31, tid >> 5, 8); // n=256, s=8
    __syncthreads();
    stage8c(P, Q, tw, tid >> 6, tid & 63, 64);// n=32, s=64
    __syncthreads();
    // radix-4, s=512, no twiddle; 2 butterflies/thread, Q -> P
#pragma unroll
    for (int h = 0; h < 2; h++) {
        int q = tid + 256*h;
        float2 u0 = Q[PDC(q)], u1 = Q[PDC(q + 512)];
        float2 u2 = Q[PDC(q + 1024)], u3 = Q[PDC(q + 1536)];
        C2 x0; x0.x = u0.x; x0.y = u0.y;
        C2 x1; x1.x = u1.x; x1.y = u1.y;
        C2 x2; x2.x = u2.x; x2.y = u2.y;
        C2 x3; x3.x = u3.x; x3.y = u3.y;
        C2 t0 = cadd(x0, x2), t1 = csub(x0, x2);
        C2 t2 = cadd(x1, x3), t3 = cmulni(csub(x1, x3));
        P[PDC(q)]        = make_float2(t0.x + t2.x, t0.y + t2.y);
        P[PDC(q + 512)]  = make_float2(t1.x + t3.x, t1.y + t3.y);
        P[PDC(q + 1024)] = make_float2(t0.x - t2.x, t0.y - t2.y);
        P[PDC(q + 1536)] = make_float2(t1.x - t3.x, t1.y - t3.y);
    }
    __syncthreads();   // result visible
}

// full 2048 FFT (general input): input AND result in P; Q scratch. 256 thr.
__device__ __forceinline__ void fft2048c(float2* P, float2* Q,
                                         const float2* __restrict__ tw) {
    int tid = threadIdx.x;
    __syncthreads();   // input visible
    stage8c(P, Q, tw, tid, 0, 1);             // n=2048, s=1
    fft2048c_tail(P, Q, tw);
}

// forward 2048 FFT for inputs zero on [1024,2048): only P[0,1024) is read.
__device__ __forceinline__ void fft2048c_fwd(float2* P, float2* Q,
                                             const float2* __restrict__ tw) {
    int tid = threadIdx.x;
    __syncthreads();   // input visible
    {
        C2 v[8];
#pragma unroll
        for (int k = 0; k < 4; k++) {
            float2 u = P[PDC(tid + 256*k)];
            v[k].x = u.x; v[k].y = u.y;
        }
        float2 tv = tw[PDC(tid)];
        C2 w1; w1.x = tv.x; w1.y = tv.y;
        bf8h(v, w1);
        int wb = 8*tid;
#pragma unroll
        for (int k = 0; k < 8; k++)
            Q[PDC(wb + k)] = make_float2(v[k].x, v[k].y);
    }
    fft2048c_tail(P, Q, tw);
}

// ---------------- kernel spectra: pack 2 d's per FFT ----------------
// stored K pre-scaled by 0.5 (unpack) * 0.5 (X-unpack fold) * 1/2048 (ifft)
#define KSCL (0.5f/4096.0f)
__global__ void fft_k_kernel() {
    __shared__ float2 A[CBUF], Bc[CBUF];
    __shared__ float2 tws[280];
    int tid = threadIdx.x;
    int dp = blockIdx.x, layer = blockIdx.y;
    int d0 = dp*2, d1 = dp*2 + 1;
    tws[PDC(tid)] = make_float2(d_twr[tid], d_twi[tid]);
    const float* k0 = d_k + (layer*Dsz + d0)*Tsz;
    const float* k1 = d_k + (layer*Dsz + d1)*Tsz;
#pragma unroll
    for (int q = 0; q < 4; q++) {
        int t = tid + 256*q;
        float v0 = (t < Tsz) ? k0[t] : 0.0f;
        float v1 = (t < Tsz) ? k1[t] : 0.0f;
        A[PDC(t)] = make_float2(v0, v1);
    }
    fft2048c_fwd(A, Bc, tws);
    float2* K0 = d_kf + (layer*Dsz + d0)*FFTN;
    float2* K1 = d_kf + (layer*Dsz + d1)*FFTN;
#pragma unroll
    for (int q = 0; q < 8; q++) {
        int f = tid + 256*q;
        int fm = (FFTN - f) & (FFTN - 1);
        float2 Zf = A[PDC(f)];
        float2 Zm = A[PDC(fm)];
        K0[f] = make_float2(KSCL*(Zf.x + Zm.x), KSCL*(Zf.y - Zm.y));
        K1[f] = make_float2(KSCL*(Zf.y + Zm.y), KSCL*(Zm.x - Zf.x));
    }
}

// ---- input projection + LN + pos-enc + L2-normalize -> d_xt2 (B,D,T) -------
// 128 threads; each owns 2 d's (tid, tid+128); tiles staged with vector ops.
__global__ void in_proj_ln_kernel(const float* __restrict__ x,
                                  const float* __restrict__ b_in,
                                  const float* __restrict__ g,
                                  const float* __restrict__ bbp) {
    int b = blockIdx.x, t0 = blockIdx.y * 20;
    int tid = threadIdx.x;          // 128
    int lane = tid & 31, w = tid >> 5;   // 4 warps
    int d0 = tid, d1 = tid + 128;
    __shared__ __align__(16) float ws[32][256];
    __shared__ __align__(8) float2 xs2[32][10];
    __shared__ float red1[4][20], red2[4][20];
    __shared__ float msh[20], ish[20];
    float acc0[20], acc1[20];
#pragma unroll
    for (int j = 0; j < 20; j++) { acc0[j] = 0.0f; acc1[j] = 0.0f; }
    for (int c0 = 0; c0 < Csz; c0 += 32) {
        __syncthreads();
        // weight tile via float4: 2048 float4s, 16 per thread
        for (int l = tid; l < 2048; l += 128) {
            int i = l >> 6, col4 = l & 63;
            float4 v = (c0 + i < Csz)
                ? *reinterpret_cast<const float4*>(d_wt + (c0 + i)*Dsz + col4*4)
                : make_float4(0.f, 0.f, 0.f, 0.f);
            *reinterpret_cast<float4*>(&ws[i][col4*4]) = v;
        }
        // x rows are float2-aligned: base (b*Csz+cc)*Tsz + t0, both even
        for (int l = tid; l < 320; l += 128) {
            int cc = l / 10, jp = l % 10;
            xs2[cc][jp] = (c0 + cc < Csz)
                ? *reinterpret_cast<const float2*>(x + (b*Csz + c0 + cc)*Tsz + t0 + 2*jp)
                : make_float2(0.f, 0.f);
        }
        __syncthreads();
#pragma unroll 4
        for (int cc = 0; cc < 32; cc++) {
            float w0 = ws[cc][d0];
            float w1 = ws[cc][d1];
#pragma unroll
            for (int jp = 0; jp < 10; jp++) {
                float2 xv = xs2[cc][jp];
                acc0[2*jp]   += w0 * xv.x;
                acc0[2*jp+1] += w0 * xv.y;
                acc1[2*jp]   += w1 * xv.x;
                acc1[2*jp+1] += w1 * xv.y;
            }
        }
    }
    float bias0 = b_in[d0], bias1 = b_in[d1];
#pragma unroll
    for (int j = 0; j < 20; j++) { acc0[j] += bias0; acc1[j] += bias1; }
    // block reduction 1: mean / var per t
#pragma unroll
    for (int j = 0; j < 20; j++) {
        float sv = acc0[j] + acc1[j];
        float sq = acc0[j]*acc0[j] + acc1[j]*acc1[j];
#pragma unroll
        for (int off = 16; off; off >>= 1) {
            sv += __shfl_xor_sync(0xffffffffu, sv, off);
            sq += __shfl_xor_sync(0xffffffffu, sq, off);
        }
        if (lane == 0) { red1[w][j] = sv; red2[w][j] = sq; }
    }
    __syncthreads();
    if (tid < 20) {
        float S = 0.f, Q = 0.f;
        for (int ww = 0; ww < 4; ww++) { S += red1[ww][tid]; Q += red2[ww][tid]; }
        float m = S * (1.0f/256.0f);
        float var = Q * (1.0f/256.0f) - m*m;
        msh[tid] = m; ish[tid] = rsqrtf(var + 1e-5f);
    }
    __syncthreads();
    float g0 = g[d0], g1 = g[d1], bv0 = bbp[d0], bv1 = bbp[d1];
#pragma unroll
    for (int j = 0; j < 20; j++) {
        float m = msh[j], is = ish[j];
        acc0[j] = (acc0[j] - m)*is*g0 + bv0 + d_pe[(t0 + j)*Dsz + d0];
        acc1[j] = (acc1[j] - m)*is*g1 + bv1 + d_pe[(t0 + j)*Dsz + d1];
    }
    // block reduction 2: L2 norm per t
#pragma unroll
    for (int j = 0; j < 20; j++) {
        float sq = acc0[j]*acc0[j] + acc1[j]*acc1[j];
#pragma unroll
        for (int off = 16; off; off >>= 1)
            sq += __shfl_xor_sync(0xffffffffu, sq, off);
        if (lane == 0) red1[w][j] = sq;
    }
    __syncthreads();
    if (tid < 20) {
        float Q = 0.f;
        for (int ww = 0; ww < 4; ww++) Q += red1[ww][tid];
        float nrm = sqrtf(Q) + 1e-8f;
        d_nrm[b*Tsz + t0 + tid] = nrm;
        ish[tid] = 1.0f / nrm;
    }
    __syncthreads();
#pragma unroll
    for (int j = 0; j < 20; j++) { acc0[j] *= ish[j]; acc1[j] *= ish[j]; }
    float4* op0 = reinterpret_cast<float4*>(d_xt2 + ((size_t)b*Dsz + d0)*Tsz + t0);
    float4* op1 = reinterpret_cast<float4*>(d_xt2 + ((size_t)b*Dsz + d1)*Tsz + t0);
#pragma unroll
    for (int q = 0; q < 5; q++) {
        op0[q] = make_float4(acc0[4*q], acc0[4*q+1], acc0[4*q+2], acc0[4*q+3]);
        op1[q] = make_float4(acc1[4*q], acc1[4*q+1], acc1[4*q+2], acc1[4*q+3]);
    }
}

// -------- FFT conv + gate + gelu + residual (z = gelu(y)+1.1h), in-place ----
// Thread owns t in [4*tid, 4*tid+4): tid<250 exactly covers Tsz=1000.
__global__ void fft_conv_kernel(int layer, const float* __restrict__ s4_D) {
    __shared__ float2 A[CBUF], Bc[CBUF];
    __shared__ float2 tws[280];
    int tid = threadIdx.x;
    int b = blockIdx.x, dp = blockIdx.y;
    int d0 = dp*2, d1 = dp*2 + 1;
    tws[PDC(tid)] = make_float2(d_twr[tid], d_twi[tid]);
    float* x0 = d_xt2 + ((size_t)b*Dsz + d0)*Tsz;
    float* x1 = d_xt2 + ((size_t)b*Dsz + d1)*Tsz;
    const float* np = d_nrm + b*Tsz;
    int t4 = tid * 4;
    bool valid = (t4 < Tsz);
    float4 fx0, fx1, fnr;
    if (valid) {
        fx0 = *reinterpret_cast<const float4*>(x0 + t4);
        fx1 = *reinterpret_cast<const float4*>(x1 + t4);
        fnr = *reinterpret_cast<const float4*>(np + t4);
    } else {
        fx0 = make_float4(0.f,0.f,0.f,0.f);
        fx1 = fx0; fnr = fx0;
    }
    // stage input into [0,1024) only; fwd FFT never reads the upper half
    if (t4 < 1024) {
        A[PDC(t4 + 0)] = make_float2(fx0.x, fx1.x);
        A[PDC(t4 + 1)] = make_float2(fx0.y, fx1.y);
        A[PDC(t4 + 2)] = make_float2(fx0.z, fx1.z);
        A[PDC(t4 + 3)] = make_float2(fx0.w, fx1.w);
    }
    fft2048c_fwd(A, Bc, tws);   // Z in A
    const float2* K0 = d_kf + (layer*Dsz + d0)*FFTN;
    const float2* K1 = d_kf + (layer*Dsz + d1)*FFTN;
    // spectral multiply with conjugate symmetry: f in [0,1024), dual write
#pragma unroll
    for (int q = 0; q < 4; q++) {
        int f = tid + 256*q;
        int fm = (FFTN - f) & (FFTN - 1);
        float2 Zf = A[PDC(f)];
        float2 Zm = A[PDC(fm)];
        C2 X0; X0.x = Zf.x + Zm.x; X0.y = Zf.y - Zm.y;
        C2 X1; X1.x = Zf.y + Zm.y; X1.y = Zm.x - Zf.x;
        float2 k0 = K0[f], k1 = K1[f];
        C2 c0; c0.x = k0.x; c0.y = k0.y;
        C2 c1; c1.x = k1.x; c1.y = k1.y;
        C2 Y0 = cmul(X0, c0);
        C2 Y1 = cmul(X1, c1);
        Bc[PDC(f)]  = make_float2(Y0.x - Y1.y, -(Y0.y + Y1.x));  // conj(S)(f)
        Bc[PDC(fm)] = make_float2(Y0.x + Y1.y,   Y0.y - Y1.x);   // conj(S)(fm)
    }
    if (tid == 0) {   // self-conjugate bin f = 1024
        float2 Zf = A[PDC(1024)];
        C2 X0; X0.x = 2.0f*Zf.x; X0.y = 0.0f;
        C2 X1; X1.x = 2.0f*Zf.y; X1.y = 0.0f;
        float2 k0 = K0[1024], k1 = K1[1024];
        C2 c0; c0.x = k0.x; c0.y = k0.y;
        C2 c1; c1.x = k1.x; c1.y = k1.y;
        C2 Y0 = cmul(X0, c0);
        C2 Y1 = cmul(X1, c1);
        Bc[PDC(1024)] = make_float2(Y0.x - Y1.y, -(Y0.y + Y1.x));
    }
    fft2048c(Bc, A, tws);   // V in Bc (scale folded into K); ifft = conj(V)
    float gate0 = 1.0f / (1.0f + __expf(-s4_D[layer*Dsz + d0]));
    float gate1 = 1.0f / (1.0f + __expf(-s4_D[layer*Dsz + d1]));
    if (valid) {
        float2 V0 = Bc[PDC(t4 + 0)];
        float2 V1 = Bc[PDC(t4 + 1)];
        float2 V2 = Bc[PDC(t4 + 2)];
        float2 V3 = Bc[PDC(t4 + 3)];
        float4 r0, r1;
        {
            float y0 =  V0.x + fx0.x*gate0, y1 = -V0.y + fx1.x*gate1;
            r0.x = 0.5f*y0*(1.0f + erff(y0*0.70710678118654752f)) + 1.1f*fx0.x*fnr.x;
            r1.x = 0.5f*y1*(1.0f + erff(y1*0.70710678118654752f)) + 1.1f*fx1.x*fnr.x;
        }
        {
            float y0 =  V1.x + fx0.y*gate0, y1 = -V1.y + fx1.y*gate1;
            r0.y = 0.5f*y0*(1.0f + erff(y0*0.70710678118654752f)) + 1.1f*fx0.y*fnr.y;
            r1.y = 0.5f*y1*(1.0f + erff(y1*0.70710678118654752f)) + 1.1f*fx1.y*fnr.y;
        }
        {
            float y0 =  V2.x + fx0.z*gate0, y1 = -V2.y + fx1.z*gate1;
            r0.z = 0.5f*y0*(1.0f + erff(y0*0.70710678118654752f)) + 1.1f*fx0.z*fnr.z;
            r1.z = 0.5f*y1*(1.0f + erff(y1*0.70710678118654752f)) + 1.1f*fx1.z*fnr.z;
        }
        {
            float y0 =  V3.x + fx0.w*gate0, y1 = -V3.y + fx1.w*gate1;
            r0.w = 0.5f*y0*(1.0f + erff(y0*0.70710678118654752f)) + 1.1f*fx0.w*fnr.w;
            r1.w = 0.5f*y1*(1.0f + erff(y1*0.70710678118654752f)) + 1.1f*fx1.w*fnr.w;
        }
        *reinterpret_cast<float4*>(x0 + t4) = r0;
        *reinterpret_cast<float4*>(x1 + t4) = r1;
    }
}

// ---- post: LN(z); last -> d_h (B,T,D); else normalized transposed + norms --
// Tile I/O vectorized: thread owns float4 runs along t (Tsz divisible by 4).
__global__ void post_ln_norm_t_kernel(int layer, int last,
                                      const float* __restrict__ ln_g,
                                      const float* __restrict__ ln_b) {
    __shared__ float tile[32][257];
    int b = blockIdx.x, t0 = blockIdx.y * 32;
    int tid = threadIdx.x, lane = tid & 31, w = tid >> 5;
    // load: 2048 float4s (32 t x 256 d), 8 per thread
#pragma unroll
    for (int it = 0; it < 8; it++) {
        int l = tid + 256*it;
        int dd = l >> 3, tq = l & 7;
        int t = t0 + tq*4;
        float4 v = (t < Tsz)
            ? *reinterpret_cast<const float4*>(d_xt2 + ((size_t)b*Dsz + dd)*Tsz + t)
            : make_float4(0.f, 0.f, 0.f, 0.f);
        tile[tq*4 + 0][dd] = v.x;
        tile[tq*4 + 1][dd] = v.y;
        tile[tq*4 + 2][dd] = v.z;
        tile[tq*4 + 3][dd] = v.w;
    }
    __syncthreads();
    const float* g  = ln_g + layer*Dsz;
    const float* bb = ln_b + layer*Dsz;
#pragma unroll
    for (int j = 0; j < 4; j++) {
        int r = w + 8*j;
        int t = t0 + r;
        if (t >= Tsz) continue;
        float z[8]; float s = 0.f, s2 = 0.f;
#pragma unroll
        for (int k = 0; k < 8; k++) {
            float zz = tile[r][lane + 32*k];
            z[k] = zz; s += zz; s2 += zz*zz;
        }
#pragma unroll
        for (int off = 16; off; off >>= 1) {
            s  += __shfl_xor_sync(0xffffffffu, s,  off);
            s2 += __shfl_xor_sync(0xffffffffu, s2, off);
        }
        float m = s * (1.0f/256.0f);
        float var = s2 * (1.0f/256.0f) - m*m;
        float is = rsqrtf(var + 1e-5f);
        if (last) {
            float* hp = d_h + ((size_t)b*Tsz + t)*Dsz;
#pragma unroll
            for (int k = 0; k < 8; k++) {
                int dd = lane + 32*k;
                hp[dd] = (z[k] - m)*is*g[dd] + bb[dd];
            }
        } else {
            float o[8]; float ss = 0.f;
#pragma unroll
            for (int k = 0; k < 8; k++) {
                int dd = lane + 32*k;
                float ov = (z[k] - m)*is*g[dd] + bb[dd];
                o[k] = ov; ss += ov*ov;
            }
#pragma unroll
            for (int off = 16; off; off >>= 1) ss += __shfl_xor_sync(0xffffffffu, ss, off);
            float nrm = sqrtf(ss) + 1e-8f;
            float invn = 1.0f / nrm;
            if (lane == 0) d_nrm[b*Tsz + t] = nrm;
#pragma unroll
            for (int k = 0; k < 8; k++) tile[r][lane + 32*k] = o[k]*invn;
        }
    }
    if (last) return;
    __syncthreads();
    // writeback: 8 float4s per thread
#pragma unroll
    for (int it = 0; it < 8; it++) {
        int l = tid + 256*it;
        int dd = l >> 3, tq = l & 7;
        int t = t0 + tq*4;
        if (t < Tsz) {
            float4 v = make_float4(tile[tq*4 + 0][dd], tile[tq*4 + 1][dd],
                                   tile[tq*4 + 2][dd], tile[tq*4 + 3][dd]);
            *reinterpret_cast<float4*>(d_xt2 + ((size_t)b*Dsz + dd)*Tsz + t) = v;
        }
    }
}

// ---------------- fused MHA pooling + head ----------------
__global__ void pool_head_kernel(const float* __restrict__ cls,
                                 const float* __restrict__ in_w,
                                 const float* __restrict__ in_b,
                                 const float* __restrict__ out_w,
                                 const float* __restrict__ out_b,
                                 const float* __restrict__ hw1,
                                 const float* __restrict__ hb1,
                                 const float* __restrict__ hw2,
                                 const float* __restrict__ hb2,
                                 float* __restrict__ out) {
    int b = blockIdx.x;
    int tid = threadIdx.x, lane = tid & 31, w = tid >> 5;
    __shared__ float Q[256];
    __shared__ float vp[8][256];
    __shared__ float sc[8][1001];
    __shared__ float ch[8];
    __shared__ float red[256];
    __shared__ float hsm[128];

    {
        float acc = in_b[tid];
        for (int c = 0; c < 256; c++) acc += cls[c] * in_w[tid*256 + c];
        Q[tid] = acc;
    }
    __syncthreads();
#pragma unroll
    for (int h = 0; h < 8; h++) {
        float acc = 0.f;
#pragma unroll
        for (int i = 0; i < 32; i++)
            acc += in_w[(256 + h*32 + i)*256 + tid] * Q[h*32 + i];
        vp[h][tid] = acc;
    }
    if (tid < 8) {
        float acc = 0.f;
        for (int i = 0; i < 32; i++) acc += in_b[256 + tid*32 + i] * Q[tid*32 + i];
        ch[tid] = acc;
    }
    __syncthreads();
    const float iss = 0.17677669529663687f; // 1/sqrt(32)
    for (int s = w; s < 1001; s += 8) {
        const float* kvr = (s == 0) ? cls : (d_h + ((size_t)b*Tsz + s - 1)*Dsz);
        float xv[8];
#pragma unroll
        for (int k = 0; k < 8; k++) xv[k] = kvr[lane*8 + k];
#pragma unroll
        for (int h = 0; h < 8; h++) {
            float a = 0.f;
#pragma unroll
            for (int k = 0; k < 8; k++) a += xv[k] * vp[h][lane*8 + k];
#pragma unroll
            for (int off = 16; off; off >>= 1) a += __shfl_xor_sync(0xffffffffu, a, off);
            if (lane == h) sc[h][s] = (a + ch[h]) * iss;
        }
    }
    __syncthreads();
    {
        int h = w;
        float mx = -1e30f;
        for (int s = lane; s < 1001; s += 32) mx = fmaxf(mx, sc[h][s]);
#pragma unroll
        for (int off = 16; off; off >>= 1) mx = fmaxf(mx, __shfl_xor_sync(0xffffffffu, mx, off));
        float sum = 0.f;
        for (int s = lane; s < 1001; s += 32) { float e = expf(sc[h][s] - mx); sc[h][s] = e; sum += e; }
#pragma unroll
        for (int off = 16; off; off >>= 1) sum += __shfl_xor_sync(0xffffffffu, sum, off);
        float invs = 1.0f / sum;
        for (int s = lane; s < 1001; s += 32) sc[h][s] *= invs;
    }
    __syncthreads();
    float pj[8];
#pragma unroll
    for (int h = 0; h < 8; h++) pj[h] = 0.f;
    for (int s = 0; s < 1001; s++) {
        float kvv = (s == 0) ? cls[tid] : d_h[((size_t)b*Tsz + s - 1)*Dsz + tid];
#pragma unroll
        for (int h = 0; h < 8; h++) pj[h] += sc[h][s] * kvv;
    }
    __syncthreads();
#pragma unroll
    for (int h = 0; h < 8; h++) vp[h][tid] = pj[h];
    __syncthreads();
    {
        int h = tid >> 5;
        float acc = in_b[512 + tid];
        for (int j = 0; j < 256; j++) acc += in_w[(512 + tid)*256 + j] * vp[h][j];
        Q[tid] = acc;
    }
    __syncthreads();
    {
        float acc = out_b[tid];
        for (int i = 0; i < 256; i++) acc += out_w[tid*256 + i] * Q[i];
        red[tid] = acc;
    }
    __syncthreads();
    if (tid < 128) {
        float acc = hb1[tid];
        for (int i = 0; i < 256; i++) acc += hw1[tid*256 + i] * red[i];
        hsm[tid] = fmaxf(acc, 0.0f);
    }
    __syncthreads();
    if (w == 0) {
        float a = 0.f;
#pragma unroll
        for (int k = 0; k < 4; k++) a += hsm[lane + 32*k] * hw2[lane + 32*k];
#pragma unroll
        for (int off = 16; off; off >>= 1) a += __shfl_xor_sync(0xffffffffu, a, off);
        if (lane == 0) out[b] = a + hb2[0];
    }
}

// ---------------- launch ----------------
extern "C" void kernel_launch(void* const* d_in, const int* in_sizes, int n_in,
                              void* d_out, int out_size) {
    const float* x        = (const float*)d_in[0];
    const float* w_in     = (const float*)d_in[1];
    const float* b_in     = (const float*)d_in[2];
    const float* ln_in_g  = (const float*)d_in[3];
    const float* ln_in_b  = (const float*)d_in[4];
    const float* s4_B     = (const float*)d_in[5];
    const float* s4_C     = (const float*)d_in[6];
    const float* s4_logdt = (const float*)d_in[7];
    const float* s4_D     = (const float*)d_in[8];
    const float* ln_g     = (const float*)d_in[9];
    const float* ln_b     = (const float*)d_in[10];
    const float* cls      = (const float*)d_in[11];
    const float* mha_in_w = (const float*)d_in[12];
    const float* mha_in_b = (const float*)d_in[13];
    const float* mha_out_w= (const float*)d_in[14];
    const float* mha_out_b= (const float*)d_in[15];
    const float* head_w1  = (const float*)d_in[16];
    const float* head_b1  = (const float*)d_in[17];
    const float* head_w2  = (const float*)d_in[18];
    const float* head_b2  = (const float*)d_in[19];
    float* out = (float*)d_out;

    setup_kernel<<<256, 256>>>(w_in);
    compute_AdE_kernel<<<NL, 512>>>(s4_logdt);
    s4_scan_kernel<<<dim3(Dsz, NL), 64>>>(s4_B, s4_C);
    fft_k_kernel<<<dim3(Dsz/2, NL), 256>>>();
    in_proj_ln_kernel<<<dim3(Bsz, 50), 128>>>(x, b_in, ln_in_g, ln_in_b);
    for (int layer = 0; layer < NL; layer++) {
        fft_conv_kernel<<<dim3(Bsz, Dsz/2), 256>>>(layer, s4_D);
        post_ln_norm_t_kernel<<<dim3(Bsz, 32), 256>>>(layer, (layer == NL-1) ? 1 : 0, ln_g, ln_b);
    }
    pool_head_kernel<<<Bsz, 256>>>(cls, mha_in_w, mha_in_b, mha_out_w, mha_out_b,
                                   head_w1, head_b1, head_w2, head_b2, out);
}